// round 3
// baseline (speedup 1.0000x reference)
#include <cuda_runtime.h>
#include <math.h>

#define NN 16384
#define LL 50
#define EE 64
#define CEDIM 128

// ---------------- device scratch (static allocations are allowed) ----------------
__device__ float g_post[NN * EE];                    // 4 MB
__device__ float g_o[(size_t)NN * LL * EE];          // 210 MB
__device__ float g_logits[NN * LL];                  // 3.3 MB
__device__ int   g_pairs[NN * LL];                   // 3.3 MB
__device__ int   g_count;

__global__ void k_reset() { g_count = 0; }

__global__ void k_build_pairs(const int* __restrict__ lengths) {
    int n = blockIdx.x * blockDim.x + threadIdx.x;
    if (n >= NN) return;
    int len = lengths[n];
    int base = atomicAdd(&g_count, len);
    for (int l = 0; l < len; ++l) g_pairs[base + l] = (n << 6) | l;
}

// ---------------- 64x64 tile GEMM, 256 threads, 4x4 register blocking ----------------
__device__ __forceinline__ void fma4(float4& a, float s, const float4 b) {
    a.x = fmaf(s, b.x, a.x); a.y = fmaf(s, b.y, a.y);
    a.z = fmaf(s, b.z, a.z); a.w = fmaf(s, b.w, a.w);
}

// out[i][f] = relu(bias[f] + sum_{k<Ka} inA[i][k]*W[k][f] + sum_{k<Kb} inB[i][k]*W[Ka+k][f])
// i in [0,64), f in [0,64). Thread: fslot=tid&15 (4 f's), islot=tid>>4 (items islot+16j).
__device__ __forceinline__ void tile_gemm(
    const float* __restrict__ W, const float* __restrict__ bias,
    const float* __restrict__ inA, int ldA, int Ka,
    const float* __restrict__ inB, int ldB, int Kb,
    float* __restrict__ out, int ldO, int tid)
{
    const int fslot = tid & 15, islot = tid >> 4;
    float4 acc[4];
    float4 b4 = ((const float4*)bias)[fslot];
    acc[0] = b4; acc[1] = b4; acc[2] = b4; acc[3] = b4;

    const float* Wp = W + fslot * 4;
    for (int k = 0; k < Ka; k += 4) {
        float4 w0 = *(const float4*)(Wp + (k + 0) * 64);
        float4 w1 = *(const float4*)(Wp + (k + 1) * 64);
        float4 w2 = *(const float4*)(Wp + (k + 2) * 64);
        float4 w3 = *(const float4*)(Wp + (k + 3) * 64);
        #pragma unroll
        for (int j = 0; j < 4; ++j) {
            float4 x = *(const float4*)(inA + (islot + 16 * j) * ldA + k);
            fma4(acc[j], x.x, w0); fma4(acc[j], x.y, w1);
            fma4(acc[j], x.z, w2); fma4(acc[j], x.w, w3);
        }
    }
    if (inB) {
        const float* Wq = W + Ka * 64 + fslot * 4;
        for (int k = 0; k < Kb; k += 4) {
            float4 w0 = *(const float4*)(Wq + (k + 0) * 64);
            float4 w1 = *(const float4*)(Wq + (k + 1) * 64);
            float4 w2 = *(const float4*)(Wq + (k + 2) * 64);
            float4 w3 = *(const float4*)(Wq + (k + 3) * 64);
            #pragma unroll
            for (int j = 0; j < 4; ++j) {
                float4 x = *(const float4*)(inB + (islot + 16 * j) * ldB + k);
                fma4(acc[j], x.x, w0); fma4(acc[j], x.y, w1);
                fma4(acc[j], x.z, w2); fma4(acc[j], x.w, w3);
            }
        }
    }
    #pragma unroll
    for (int j = 0; j < 4; ++j) {
        float4 v = acc[j];
        v.x = fmaxf(v.x, 0.f); v.y = fmaxf(v.y, 0.f);
        v.z = fmaxf(v.z, 0.f); v.w = fmaxf(v.w, 0.f);
        *(float4*)(out + (islot + 16 * j) * ldO + fslot * 4) = v;
    }
}

// A2 layer + A3 logit: a2 = relu(W*a1+b); logit = a2 . A3 + bA3 (a2 stays in registers)
__device__ __forceinline__ void tile_a2_logit(
    const float* __restrict__ W, const float* __restrict__ bias,
    const float* __restrict__ inA, int ldA, int Ka,
    const float* __restrict__ A3, float bA3,
    const int* __restrict__ pn, const int* __restrict__ pl, int tid)
{
    const int fslot = tid & 15, islot = tid >> 4;
    float4 acc[4];
    float4 b4 = ((const float4*)bias)[fslot];
    acc[0] = b4; acc[1] = b4; acc[2] = b4; acc[3] = b4;

    const float* Wp = W + fslot * 4;
    for (int k = 0; k < Ka; k += 4) {
        float4 w0 = *(const float4*)(Wp + (k + 0) * 64);
        float4 w1 = *(const float4*)(Wp + (k + 1) * 64);
        float4 w2 = *(const float4*)(Wp + (k + 2) * 64);
        float4 w3 = *(const float4*)(Wp + (k + 3) * 64);
        #pragma unroll
        for (int j = 0; j < 4; ++j) {
            float4 x = *(const float4*)(inA + (islot + 16 * j) * ldA + k);
            fma4(acc[j], x.x, w0); fma4(acc[j], x.y, w1);
            fma4(acc[j], x.z, w2); fma4(acc[j], x.w, w3);
        }
    }
    float4 a3 = ((const float4*)A3)[fslot];
    #pragma unroll
    for (int j = 0; j < 4; ++j) {
        float p = fmaxf(acc[j].x, 0.f) * a3.x + fmaxf(acc[j].y, 0.f) * a3.y +
                  fmaxf(acc[j].z, 0.f) * a3.z + fmaxf(acc[j].w, 0.f) * a3.w;
        #pragma unroll
        for (int off = 8; off >= 1; off >>= 1)
            p += __shfl_xor_sync(0xffffffffu, p, off);   // reduce over the 16 fslot lanes
        if (fslot == 0) {
            int it = islot + 16 * j;
            g_logits[pn[it] * LL + pl[it]] = p + bA3;
        }
    }
}

// ---------------- post kernel: post = relu(content[pr_content] @ We + bWe) ----------------
struct SmemPost {
    float We[128 * 64];
    float bWe[64];
    float in[64 * 128];
    int   cix[64];
};

__global__ void __launch_bounds__(256, 1) k_post(
    const float* __restrict__ content, const float* __restrict__ Weg,
    const float* __restrict__ bWeg, const int* __restrict__ pr_content)
{
    extern __shared__ float smem_raw[];
    SmemPost& s = *(SmemPost*)smem_raw;
    int tid = threadIdx.x;
    for (int i = tid; i < 128 * 64; i += 256) s.We[i] = Weg[i];
    if (tid < 64) { s.bWe[tid] = bWeg[tid]; s.cix[tid] = pr_content[blockIdx.x * 64 + tid]; }
    __syncthreads();
    for (int v = tid; v < 64 * 32; v += 256) {
        int it = v >> 5, sub = v & 31;
        ((float4*)(s.in + it * 128))[sub] =
            ((const float4*)(content + (size_t)s.cix[it] * 128))[sub];
    }
    __syncthreads();
    tile_gemm(s.We, s.bWe, s.in, 128, 128, nullptr, 0, 0,
              g_post + (size_t)blockIdx.x * 64 * 64, 64, tid);
}

// ---------------- main kernel: per-pair x -> o -> a1 -> a2 -> logit ----------------
struct SmemMain {
    float W1[128 * 64];
    float A1[128 * 64];
    float W2[64 * 64];
    float A2[64 * 64];
    float b1[64], b2[64], bA1[64], bA2[64], A3[64];
    float in[64 * 128];
    float act[64 * 64];
    float o[64 * 64];
    float post[64 * 64];
    int pn[64], pl[64], uix[64], rix[64];
};

__global__ void __launch_bounds__(256, 1) k_main(
    const float* __restrict__ u2e, const float* __restrict__ r2e,
    const float* __restrict__ W1g, const float* __restrict__ b1g,
    const float* __restrict__ W2g, const float* __restrict__ b2g,
    const float* __restrict__ A1g, const float* __restrict__ bA1g,
    const float* __restrict__ A2g, const float* __restrict__ bA2g,
    const float* __restrict__ A3g, const float* __restrict__ bA3g,
    const int* __restrict__ pu, const int* __restrict__ pr)
{
    extern __shared__ float smem_raw[];
    SmemMain& s = *(SmemMain*)smem_raw;
    int tid = threadIdx.x;

    for (int i = tid; i < 128 * 64; i += 256) { s.W1[i] = W1g[i]; s.A1[i] = A1g[i]; }
    for (int i = tid; i < 64 * 64; i += 256)  { s.W2[i] = W2g[i]; s.A2[i] = A2g[i]; }
    if (tid < 64) {
        s.b1[tid] = b1g[tid]; s.b2[tid] = b2g[tid];
        s.bA1[tid] = bA1g[tid]; s.bA2[tid] = bA2g[tid]; s.A3[tid] = A3g[tid];
    }
    float bA3 = bA3g[0];
    __syncthreads();

    int total = g_count;
    int ntiles = (total + 63) >> 6;

    for (int t = blockIdx.x; t < ntiles; t += gridDim.x) {
        int e0 = t * 64;
        if (tid < 64) {
            int e = e0 + tid;
            int pair = (e < total) ? g_pairs[e] : 0;   // pad -> (0,0), benign duplicate
            int n = pair >> 6, l = pair & 63;
            s.pn[tid] = n; s.pl[tid] = l;
            s.uix[tid] = pu[n * LL + l];
            s.rix[tid] = pr[n * LL + l];
        }
        __syncthreads();

        // gather [u;r] rows (64x128) and post rows (64x64)
        for (int v = tid; v < 64 * 32 + 64 * 16; v += 256) {
            if (v < 64 * 32) {
                int it = v >> 5, sub = v & 31;
                float4 val;
                if (sub < 16) val = ((const float4*)(u2e + (size_t)s.uix[it] * 64))[sub];
                else          val = ((const float4*)(r2e + (size_t)s.rix[it] * 64))[sub - 16];
                ((float4*)(s.in + it * 128))[sub] = val;
            } else {
                int w = v - 64 * 32; int it = w >> 4, sub = w & 15;
                ((float4*)(s.post + it * 64))[sub] =
                    ((const float4*)(g_post + s.pn[it] * 64))[sub];
            }
        }
        __syncthreads();

        tile_gemm(s.W1, s.b1, s.in, 128, 128, nullptr, 0, 0, s.act, 64, tid);  // x
        __syncthreads();
        tile_gemm(s.W2, s.b2, s.act, 64, 64, nullptr, 0, 0, s.o, 64, tid);     // o
        __syncthreads();

        // write o to global (read later by finalize), then A1 (both only read s.o)
        for (int v = tid; v < 64 * 16; v += 256) {
            int it = v >> 4, sub = v & 15;
            ((float4*)(g_o + ((size_t)s.pn[it] * LL + s.pl[it]) * 64))[sub] =
                ((const float4*)(s.o + it * 64))[sub];
        }
        tile_gemm(s.A1, s.bA1, s.o, 64, 64, s.post, 64, 64, s.act, 64, tid);   // a1
        __syncthreads();
        tile_a2_logit(s.A2, s.bA2, s.act, 64, 64, s.A3, bA3, s.pn, s.pl, tid); // logit
        __syncthreads();
    }
}

// ---------------- finalize: softmax + hist + output layer ----------------
struct SmemFin {
    float Ow[128 * 64];
    float bOw[64];
    float att[64];
    float red[256];
    float hist[64];
    float post[64];
};

__global__ void __launch_bounds__(256, 1) k_fin(
    const float* __restrict__ Owg, const float* __restrict__ bOwg,
    const int* __restrict__ lengths, float* __restrict__ out)
{
    extern __shared__ float smem_raw[];
    SmemFin& s = *(SmemFin*)smem_raw;
    int tid = threadIdx.x;
    for (int i = tid; i < 128 * 64; i += 256) s.Ow[i] = Owg[i];
    if (tid < 64) s.bOw[tid] = bOwg[tid];
    __syncthreads();

    for (int n = blockIdx.x; n < NN; n += gridDim.x) {
        int len = lengths[n];
        if (tid < 32) {
            int lane = tid;
            float l0 = (lane < len)      ? g_logits[n * LL + lane]      : -INFINITY;
            float l1 = (lane + 32 < len) ? g_logits[n * LL + lane + 32] : -INFINITY;
            float m = fmaxf(l0, l1);
            #pragma unroll
            for (int off = 16; off >= 1; off >>= 1)
                m = fmaxf(m, __shfl_xor_sync(0xffffffffu, m, off));
            float e0 = (lane < len)      ? expf(l0 - m) : 0.f;
            float e1 = (lane + 32 < len) ? expf(l1 - m) : 0.f;
            float sum = e0 + e1;
            #pragma unroll
            for (int off = 16; off >= 1; off >>= 1)
                sum += __shfl_xor_sync(0xffffffffu, sum, off);
            float inv = 1.f / sum;
            s.att[lane] = e0 * inv; s.att[lane + 32] = e1 * inv;
        }
        if (tid >= 64 && tid < 128) s.post[tid - 64] = g_post[n * 64 + (tid - 64)];
        __syncthreads();

        int f = tid & 63, g = tid >> 6;
        float partial = 0.f;
        for (int l = g; l < len; l += 4)
            partial += s.att[l] * g_o[((size_t)n * LL + l) * 64 + f];
        s.red[g * 64 + f] = partial;
        __syncthreads();
        if (tid < 64)
            s.hist[tid] = s.red[tid] + s.red[64 + tid] + s.red[128 + tid] + s.red[192 + tid];
        __syncthreads();

        float p2 = 0.f;
        int k0 = g * 32;
        #pragma unroll 8
        for (int k = k0; k < k0 + 32; ++k) {
            float x = (k < 64) ? s.hist[k] : s.post[k - 64];
            p2 = fmaf(x, s.Ow[k * 64 + f], p2);
        }
        s.red[g * 64 + f] = p2;
        __syncthreads();
        if (tid < 64)
            out[n * 64 + tid] = fmaxf(
                s.bOw[tid] + s.red[tid] + s.red[64 + tid] + s.red[128 + tid] + s.red[192 + tid],
                0.f);
        __syncthreads();
    }
}

// ---------------- launch ----------------
extern "C" void kernel_launch(void* const* d_in, const int* in_sizes, int n_in,
                              void* d_out, int out_size)
{
    const float* u2e     = (const float*)d_in[0];
    const float* r2e     = (const float*)d_in[1];
    const float* content = (const float*)d_in[2];
    const float* We_w = (const float*)d_in[3];  const float* We_b = (const float*)d_in[4];
    const float* W1_w = (const float*)d_in[5];  const float* W1_b = (const float*)d_in[6];
    const float* W2_w = (const float*)d_in[7];  const float* W2_b = (const float*)d_in[8];
    const float* A1_w = (const float*)d_in[9];  const float* A1_b = (const float*)d_in[10];
    const float* A2_w = (const float*)d_in[11]; const float* A2_b = (const float*)d_in[12];
    const float* A3_w = (const float*)d_in[13]; const float* A3_b = (const float*)d_in[14];
    const float* Ow_w = (const float*)d_in[15]; const float* Ow_b = (const float*)d_in[16];
    const int* pu      = (const int*)d_in[18];
    const int* pr      = (const int*)d_in[19];
    const int* lengths = (const int*)d_in[20];
    const int* prc     = (const int*)d_in[21];
    float* out = (float*)d_out;

    static int nsm = 0;
    if (nsm == 0) {
        cudaDeviceGetAttribute(&nsm, cudaDevAttrMultiProcessorCount, 0);
        cudaFuncSetAttribute(k_main, cudaFuncAttributeMaxDynamicSharedMemorySize, (int)sizeof(SmemMain));
        cudaFuncSetAttribute(k_post, cudaFuncAttributeMaxDynamicSharedMemorySize, (int)sizeof(SmemPost));
        cudaFuncSetAttribute(k_fin,  cudaFuncAttributeMaxDynamicSharedMemorySize, (int)sizeof(SmemFin));
    }

    k_reset<<<1, 1>>>();
    k_build_pairs<<<NN / 256, 256>>>(lengths);
    k_post<<<NN / 64, 256, sizeof(SmemPost)>>>(content, We_w, We_b, prc);
    k_main<<<nsm, 256, sizeof(SmemMain)>>>(u2e, r2e, W1_w, W1_b, W2_w, W2_b,
                                           A1_w, A1_b, A2_w, A2_b, A3_w, A3_b, pu, pr);
    k_fin<<<nsm, 256, sizeof(SmemFin)>>>(Ow_w, Ow_b, lengths, out);
}

// round 4
// speedup vs baseline: 1.1832x; 1.1832x over previous
#include <cuda_runtime.h>
#include <math.h>

#define NN 16384
#define LL 50
#define EE 64
#define CEDIM 128

// ---------------- device scratch ----------------
__device__ float g_post[NN * EE];                    // 4 MB
__device__ float g_o[(size_t)NN * LL * EE];          // 210 MB
__device__ float g_logits[NN * LL];                  // 3.3 MB
__device__ int   g_pairs[NN * LL];                   // 3.3 MB
__device__ int   g_count;

__global__ void k_reset() { g_count = 0; }

__global__ void k_build_pairs(const int* __restrict__ lengths) {
    int n = blockIdx.x * blockDim.x + threadIdx.x;
    if (n >= NN) return;
    int len = lengths[n];
    int base = atomicAdd(&g_count, len);
    for (int l = 0; l < len; ++l) g_pairs[base + l] = (n << 6) | l;
}

// ---------------- tile GEMM: ITEMS = 4*ISTR items, 64 feats, 4x4 register blocking ----
__device__ __forceinline__ void fma4(float4& a, float s, const float4 b) {
    a.x = fmaf(s, b.x, a.x); a.y = fmaf(s, b.y, a.y);
    a.z = fmaf(s, b.z, a.z); a.w = fmaf(s, b.w, a.w);
}

// out[i][f] = relu(bias[f] + sum_k in[i][k]*W[k][f]); i in [0,4*ISTR), f in [0,64)
// fslot = tid&15 (4 f's), islot = tid>>4 in [0,ISTR), items islot + ISTR*j
template <int ISTR>
__device__ __forceinline__ void tile_gemm(
    const float* __restrict__ W, const float* __restrict__ bias,
    const float* __restrict__ inA, int ldA, int Ka,
    float* __restrict__ out, int ldO, int tid)
{
    const int fslot = tid & 15, islot = tid >> 4;
    float4 acc[4];
    float4 b4 = ((const float4*)bias)[fslot];
    acc[0] = b4; acc[1] = b4; acc[2] = b4; acc[3] = b4;

    const float* Wp = W + fslot * 4;
    for (int k = 0; k < Ka; k += 4) {
        float4 w0 = *(const float4*)(Wp + (k + 0) * 64);
        float4 w1 = *(const float4*)(Wp + (k + 1) * 64);
        float4 w2 = *(const float4*)(Wp + (k + 2) * 64);
        float4 w3 = *(const float4*)(Wp + (k + 3) * 64);
        #pragma unroll
        for (int j = 0; j < 4; ++j) {
            float4 x = *(const float4*)(inA + (islot + ISTR * j) * ldA + k);
            fma4(acc[j], x.x, w0); fma4(acc[j], x.y, w1);
            fma4(acc[j], x.z, w2); fma4(acc[j], x.w, w3);
        }
    }
    #pragma unroll
    for (int j = 0; j < 4; ++j) {
        float4 v = acc[j];
        v.x = fmaxf(v.x, 0.f); v.y = fmaxf(v.y, 0.f);
        v.z = fmaxf(v.z, 0.f); v.w = fmaxf(v.w, 0.f);
        *(float4*)(out + (islot + ISTR * j) * ldO + fslot * 4) = v;
    }
}

// A2 layer + A3 logit: a2 = relu(W*a1+b); logit = a2 . A3 + bA3 (a2 stays in registers)
template <int ISTR>
__device__ __forceinline__ void tile_a2_logit(
    const float* __restrict__ W, const float* __restrict__ bias,
    const float* __restrict__ inA, int ldA,
    const float* __restrict__ A3, float bA3,
    const int* __restrict__ pn, const int* __restrict__ pl, int tid)
{
    const int fslot = tid & 15, islot = tid >> 4;
    float4 acc[4];
    float4 b4 = ((const float4*)bias)[fslot];
    acc[0] = b4; acc[1] = b4; acc[2] = b4; acc[3] = b4;

    const float* Wp = W + fslot * 4;
    for (int k = 0; k < 64; k += 4) {
        float4 w0 = *(const float4*)(Wp + (k + 0) * 64);
        float4 w1 = *(const float4*)(Wp + (k + 1) * 64);
        float4 w2 = *(const float4*)(Wp + (k + 2) * 64);
        float4 w3 = *(const float4*)(Wp + (k + 3) * 64);
        #pragma unroll
        for (int j = 0; j < 4; ++j) {
            float4 x = *(const float4*)(inA + (islot + ISTR * j) * ldA + k);
            fma4(acc[j], x.x, w0); fma4(acc[j], x.y, w1);
            fma4(acc[j], x.z, w2); fma4(acc[j], x.w, w3);
        }
    }
    float4 a3 = ((const float4*)A3)[fslot];
    #pragma unroll
    for (int j = 0; j < 4; ++j) {
        float p = fmaxf(acc[j].x, 0.f) * a3.x + fmaxf(acc[j].y, 0.f) * a3.y +
                  fmaxf(acc[j].z, 0.f) * a3.z + fmaxf(acc[j].w, 0.f) * a3.w;
        #pragma unroll
        for (int off = 8; off >= 1; off >>= 1)
            p += __shfl_xor_sync(0xffffffffu, p, off);   // reduce over the 16 fslot lanes
        if (fslot == 0) {
            int it = islot + ISTR * j;
            g_logits[pn[it] * LL + pl[it]] = p + bA3;
        }
    }
}

// ---------------- post kernel: post = relu(content[pr_content] @ We + bWe) ----------------
struct SmemPost {
    float We[128 * 64];
    float bWe[64];
    float in[64 * 128];
    int   cix[64];
};

__global__ void __launch_bounds__(256, 1) k_post(
    const float* __restrict__ content, const float* __restrict__ Weg,
    const float* __restrict__ bWeg, const int* __restrict__ pr_content)
{
    extern __shared__ float smem_raw[];
    SmemPost& s = *(SmemPost*)smem_raw;
    int tid = threadIdx.x;
    for (int i = tid; i < 128 * 64; i += 256) s.We[i] = Weg[i];
    if (tid < 64) { s.bWe[tid] = bWeg[tid]; s.cix[tid] = pr_content[blockIdx.x * 64 + tid]; }
    __syncthreads();
    for (int v = tid; v < 64 * 32; v += 256) {
        int it = v >> 5, sub = v & 31;
        ((float4*)(s.in + it * 128))[sub] =
            ((const float4*)(content + (size_t)s.cix[it] * 128))[sub];
    }
    __syncthreads();
    tile_gemm<16>(s.We, s.bWe, s.in, 128, 128,
                  g_post + (size_t)blockIdx.x * 64 * 64, 64, tid);
}

// ---------------- main kernel: 512 threads, 128-pair tiles ----------------
struct SmemMain {
    float W1[128 * 64];
    float A1[128 * 64];
    float W2[64 * 64];
    float A2[64 * 64];
    float b1[64], b2[64], bA1[64], bA2[64], A3[64];
    float in[128 * 128];     // [u|r], later [o|post]
    float act[128 * 64];     // x, later a1
    int pn[128], pl[128], uix[128], rix[128];
};

__global__ void __launch_bounds__(512, 1) k_main(
    const float* __restrict__ u2e, const float* __restrict__ r2e,
    const float* __restrict__ W1g, const float* __restrict__ b1g,
    const float* __restrict__ W2g, const float* __restrict__ b2g,
    const float* __restrict__ A1g, const float* __restrict__ bA1g,
    const float* __restrict__ A2g, const float* __restrict__ bA2g,
    const float* __restrict__ A3g, const float* __restrict__ bA3g,
    const int* __restrict__ pu, const int* __restrict__ pr)
{
    extern __shared__ float smem_raw[];
    SmemMain& s = *(SmemMain*)smem_raw;
    int tid = threadIdx.x;

    for (int i = tid; i < 128 * 64; i += 512) { s.W1[i] = W1g[i]; s.A1[i] = A1g[i]; }
    for (int i = tid; i < 64 * 64; i += 512)  { s.W2[i] = W2g[i]; s.A2[i] = A2g[i]; }
    if (tid < 64) {
        s.b1[tid] = b1g[tid]; s.b2[tid] = b2g[tid];
        s.bA1[tid] = bA1g[tid]; s.bA2[tid] = bA2g[tid]; s.A3[tid] = A3g[tid];
    }
    float bA3 = bA3g[0];
    __syncthreads();

    int total = g_count;
    int ntiles = (total + 127) >> 7;

    for (int t = blockIdx.x; t < ntiles; t += gridDim.x) {
        int e0 = t << 7;
        if (tid < 128) {
            int e = e0 + tid;
            int pair = (e < total) ? g_pairs[e] : 0;   // pad -> (0,0), benign duplicate
            int n = pair >> 6, l = pair & 63;
            s.pn[tid] = n; s.pl[tid] = l;
            s.uix[tid] = pu[n * LL + l];
            s.rix[tid] = pr[n * LL + l];
        }
        __syncthreads();

        // gather [u;r] rows: 128 items x 32 float4
        for (int v = tid; v < 128 * 32; v += 512) {
            int it = v >> 5, sub = v & 31;
            float4 val;
            if (sub < 16) val = ((const float4*)(u2e + (size_t)s.uix[it] * 64))[sub];
            else          val = ((const float4*)(r2e + (size_t)s.rix[it] * 64))[sub - 16];
            ((float4*)(s.in + it * 128))[sub] = val;
        }
        __syncthreads();

        tile_gemm<32>(s.W1, s.b1, s.in, 128, 128, s.act, 64, tid);   // x = relu([u;r]W1+b1)
        __syncthreads();
        // o = relu(x W2 + b2) -> in[:,0:64]; gather post -> in[:,64:128]
        tile_gemm<32>(s.W2, s.b2, s.act, 64, 64, s.in, 128, tid);
        for (int v = tid; v < 128 * 16; v += 512) {
            int it = v >> 4, sub = v & 15;
            ((float4*)(s.in + it * 128 + 64))[sub] =
                ((const float4*)(g_post + s.pn[it] * 64))[sub];
        }
        __syncthreads();

        // write o to global (read by finalize); a1 = relu([o;post] A1 + bA1)
        for (int v = tid; v < 128 * 16; v += 512) {
            int it = v >> 4, sub = v & 15;
            ((float4*)(g_o + ((size_t)s.pn[it] * LL + s.pl[it]) * 64))[sub] =
                ((const float4*)(s.in + it * 128))[sub];
        }
        tile_gemm<32>(s.A1, s.bA1, s.in, 128, 128, s.act, 64, tid);
        __syncthreads();
        tile_a2_logit<32>(s.A2, s.bA2, s.act, 64, s.A3, bA3, s.pn, s.pl, tid);
        __syncthreads();   // protect pn/pl/in before next tile
    }
}

// ---------------- finalize: softmax + hist + output layer; 8 nodes per block-iter ----------
struct SmemFin {
    float Ow[128 * 64];
    float bOw[64];
    float att[8][64];
    float in[8][128];        // [hist | post]
    float red[8][4][64];
};

__global__ void __launch_bounds__(512, 1) k_fin(
    const float* __restrict__ Owg, const float* __restrict__ bOwg,
    const int* __restrict__ lengths, float* __restrict__ out)
{
    extern __shared__ float smem_raw[];
    SmemFin& s = *(SmemFin*)smem_raw;
    int tid = threadIdx.x;
    for (int i = tid; i < 128 * 64; i += 512) s.Ow[i] = Owg[i];
    if (tid < 64) s.bOw[tid] = bOwg[tid];
    __syncthreads();

    const int g = tid >> 6;          // node group 0..7
    const int gt = tid & 63;         // thread within group

    for (int base = blockIdx.x * 8; base < NN; base += gridDim.x * 8) {
        int n = base + g;
        int len = lengths[n];

        if (gt < 32) {
            // softmax over logits (one warp per node)
            int lane = gt;
            float l0 = (lane < len)      ? g_logits[n * LL + lane]      : -INFINITY;
            float l1 = (lane + 32 < len) ? g_logits[n * LL + lane + 32] : -INFINITY;
            float m = fmaxf(l0, l1);
            #pragma unroll
            for (int off = 16; off >= 1; off >>= 1)
                m = fmaxf(m, __shfl_xor_sync(0xffffffffu, m, off));
            float e0 = (lane < len)      ? expf(l0 - m) : 0.f;
            float e1 = (lane + 32 < len) ? expf(l1 - m) : 0.f;
            float sum = e0 + e1;
            #pragma unroll
            for (int off = 16; off >= 1; off >>= 1)
                sum += __shfl_xor_sync(0xffffffffu, sum, off);
            float inv = 1.f / sum;
            s.att[g][lane] = e0 * inv; s.att[g][lane + 32] = e1 * inv;
        } else {
            // load post into in[g][64:128] (second warp of group)
            int f0 = gt - 32;
            s.in[g][64 + f0]      = g_post[n * 64 + f0];
            s.in[g][64 + f0 + 32] = g_post[n * 64 + f0 + 32];
        }
        __syncthreads();

        // hist[f] = sum_l att[l] * o[n][l][f]
        {
            float h = 0.f;
            const float* orow = g_o + (size_t)n * LL * 64 + gt;
            #pragma unroll 2
            for (int l = 0; l < len; ++l)
                h = fmaf(s.att[g][l], orow[(size_t)l * 64], h);
            s.in[g][gt] = h;
        }
        __syncthreads();

        // out = relu([hist;post] @ Ow + bOw): 4-way k-split, float4 weights
        {
            int fslot = gt & 15, kslot = gt >> 4;
            float4 acc = make_float4(0.f, 0.f, 0.f, 0.f);
            const float* Wp = s.Ow + fslot * 4;
            #pragma unroll 8
            for (int k = kslot * 32; k < kslot * 32 + 32; ++k) {
                float xv = s.in[g][k];
                float4 w = *(const float4*)(Wp + k * 64);
                acc.x = fmaf(xv, w.x, acc.x); acc.y = fmaf(xv, w.y, acc.y);
                acc.z = fmaf(xv, w.z, acc.z); acc.w = fmaf(xv, w.w, acc.w);
            }
            *(float4*)(&s.red[g][kslot][fslot * 4]) = acc;
        }
        __syncthreads();

        {
            float v = s.bOw[gt] + s.red[g][0][gt] + s.red[g][1][gt]
                                + s.red[g][2][gt] + s.red[g][3][gt];
            out[n * 64 + gt] = fmaxf(v, 0.f);
        }
        __syncthreads();   // protect att/in/red before next iteration
    }
}

// ---------------- launch ----------------
extern "C" void kernel_launch(void* const* d_in, const int* in_sizes, int n_in,
                              void* d_out, int out_size)
{
    const float* u2e     = (const float*)d_in[0];
    const float* r2e     = (const float*)d_in[1];
    const float* content = (const float*)d_in[2];
    const float* We_w = (const float*)d_in[3];  const float* We_b = (const float*)d_in[4];
    const float* W1_w = (const float*)d_in[5];  const float* W1_b = (const float*)d_in[6];
    const float* W2_w = (const float*)d_in[7];  const float* W2_b = (const float*)d_in[8];
    const float* A1_w = (const float*)d_in[9];  const float* A1_b = (const float*)d_in[10];
    const float* A2_w = (const float*)d_in[11]; const float* A2_b = (const float*)d_in[12];
    const float* A3_w = (const float*)d_in[13]; const float* A3_b = (const float*)d_in[14];
    const float* Ow_w = (const float*)d_in[15]; const float* Ow_b = (const float*)d_in[16];
    const int* pu      = (const int*)d_in[18];
    const int* pr      = (const int*)d_in[19];
    const int* lengths = (const int*)d_in[20];
    const int* prc     = (const int*)d_in[21];
    float* out = (float*)d_out;

    static int nsm = 0;
    if (nsm == 0) {
        cudaDeviceGetAttribute(&nsm, cudaDevAttrMultiProcessorCount, 0);
        cudaFuncSetAttribute(k_main, cudaFuncAttributeMaxDynamicSharedMemorySize, (int)sizeof(SmemMain));
        cudaFuncSetAttribute(k_post, cudaFuncAttributeMaxDynamicSharedMemorySize, (int)sizeof(SmemPost));
        cudaFuncSetAttribute(k_fin,  cudaFuncAttributeMaxDynamicSharedMemorySize, (int)sizeof(SmemFin));
    }

    k_reset<<<1, 1>>>();
    k_build_pairs<<<NN / 256, 256>>>(lengths);
    k_post<<<NN / 64, 256, sizeof(SmemPost)>>>(content, We_w, We_b, prc);
    k_main<<<nsm, 512, sizeof(SmemMain)>>>(u2e, r2e, W1_w, W1_b, W2_w, W2_b,
                                           A1_w, A1_b, A2_w, A2_b, A3_w, A3_b, pu, pr);
    k_fin<<<nsm, 512, sizeof(SmemFin)>>>(Ow_w, Ow_b, lengths, out);
}

// round 5
// speedup vs baseline: 1.2899x; 1.0902x over previous
#include <cuda_runtime.h>
#include <math.h>

#define NN 16384
#define LL 50
#define EE 64
#define CEDIM 128

typedef unsigned long long ull;

// ---------------- device scratch ----------------
__device__ float g_post[NN * EE];                    // 4 MB
__device__ float g_o[(size_t)NN * LL * EE];          // 210 MB
__device__ float g_logits[NN * LL];                  // 3.3 MB
__device__ int   g_pairs[NN * LL];                   // 3.3 MB
__device__ int   g_count;

__global__ void k_reset() { g_count = 0; }

__global__ void k_build_pairs(const int* __restrict__ lengths) {
    int n = blockIdx.x * blockDim.x + threadIdx.x;
    if (n >= NN) return;
    int len = lengths[n];
    int base = atomicAdd(&g_count, len);
    for (int l = 0; l < len; ++l) g_pairs[base + l] = (n << 6) | l;
}

// ---------------- packed f32x2 FMA ----------------
__device__ __forceinline__ void ffma2(ull& d, ull a, ull b) {
    asm("fma.rn.f32x2 %0, %1, %2, %0;" : "+l"(d) : "l"(a), "l"(b));
}
__device__ __forceinline__ float hsum2(ull v) {
    float2 p = *(float2*)&v;
    return p.x + p.y;
}

// Transposed-weight smem layout:
//   element (f, k) at float offset (k>>2)*256 + ((f>>2) + (f&3)*16)*4 + (k&3)
// A lane loading the 16B block (f, 4k..4k+3) uses addr = kblk*1024B + fslot*16B + ff*256B,
// so the 16 fslot lanes hit banks 0,4,...,28 (clean 2-phase for 256B). Size = K*64 floats.
__device__ __forceinline__ void load_wt(const float* __restrict__ Wg, float* __restrict__ Wt,
                                        int K, int tid, int nthr) {
    for (int i = tid; i < K * 64; i += nthr) {
        int k = i >> 6, f = i & 63;
        Wt[(k >> 2) * 256 + ((f >> 2) + (f & 3) * 16) * 4 + (k & 3)] = Wg[i];
    }
}

// ---------------- packed tile GEMM ----------------
// out[i][f] = relu(bias[f] + sum_k in[i][k]*W[k][f]); 4*ISTR items, 64 feats.
// fslot = tid&15 (4 f's), islot = tid>>4 in [0,ISTR), items islot + ISTR*j.
template <int ISTR>
__device__ __forceinline__ void tile_gemm_p(
    const float* __restrict__ Wt, const float* __restrict__ bias,
    const float* __restrict__ inA, int ldA, int K,
    float* __restrict__ out, int ldO, int tid)
{
    const int fslot = tid & 15, islot = tid >> 4;
    ull acc[4][4];
    #pragma unroll
    for (int j = 0; j < 4; ++j)
        #pragma unroll
        for (int ff = 0; ff < 4; ++ff) acc[j][ff] = 0ull;

    const float* wp = Wt + fslot * 4;
    const float* xp = inA + islot * ldA;
    const int nkb = K >> 2;
    #pragma unroll 4
    for (int kb = 0; kb < nkb; ++kb) {
        ulonglong2 w[4];
        #pragma unroll
        for (int ff = 0; ff < 4; ++ff)
            w[ff] = *(const ulonglong2*)(wp + kb * 256 + ff * 64);
        ulonglong2 x[4];
        #pragma unroll
        for (int j = 0; j < 4; ++j)
            x[j] = *(const ulonglong2*)(xp + j * (ISTR * ldA) + kb * 4);
        #pragma unroll
        for (int j = 0; j < 4; ++j)
            #pragma unroll
            for (int ff = 0; ff < 4; ++ff) {
                ffma2(acc[j][ff], x[j].x, w[ff].x);
                ffma2(acc[j][ff], x[j].y, w[ff].y);
            }
    }
    float4 b4 = ((const float4*)bias)[fslot];
    #pragma unroll
    for (int j = 0; j < 4; ++j) {
        float4 v;
        v.x = fmaxf(hsum2(acc[j][0]) + b4.x, 0.f);
        v.y = fmaxf(hsum2(acc[j][1]) + b4.y, 0.f);
        v.z = fmaxf(hsum2(acc[j][2]) + b4.z, 0.f);
        v.w = fmaxf(hsum2(acc[j][3]) + b4.w, 0.f);
        *(float4*)(out + (islot + ISTR * j) * ldO + fslot * 4) = v;
    }
}

// A2 layer + A3 logit: a2 = relu(W*a1+b); logit = a2 . A3 + bA3 (a2 stays in registers)
template <int ISTR>
__device__ __forceinline__ void tile_a2_logit_p(
    const float* __restrict__ Wt, const float* __restrict__ bias,
    const float* __restrict__ inA, int ldA,
    const float* __restrict__ A3, float bA3,
    const int* __restrict__ pn, const int* __restrict__ pl, int tid)
{
    const int fslot = tid & 15, islot = tid >> 4;
    ull acc[4][4];
    #pragma unroll
    for (int j = 0; j < 4; ++j)
        #pragma unroll
        for (int ff = 0; ff < 4; ++ff) acc[j][ff] = 0ull;

    const float* wp = Wt + fslot * 4;
    const float* xp = inA + islot * ldA;
    #pragma unroll 4
    for (int kb = 0; kb < 16; ++kb) {
        ulonglong2 w[4];
        #pragma unroll
        for (int ff = 0; ff < 4; ++ff)
            w[ff] = *(const ulonglong2*)(wp + kb * 256 + ff * 64);
        ulonglong2 x[4];
        #pragma unroll
        for (int j = 0; j < 4; ++j)
            x[j] = *(const ulonglong2*)(xp + j * (ISTR * ldA) + kb * 4);
        #pragma unroll
        for (int j = 0; j < 4; ++j)
            #pragma unroll
            for (int ff = 0; ff < 4; ++ff) {
                ffma2(acc[j][ff], x[j].x, w[ff].x);
                ffma2(acc[j][ff], x[j].y, w[ff].y);
            }
    }
    float4 b4 = ((const float4*)bias)[fslot];
    float4 a3 = ((const float4*)A3)[fslot];
    #pragma unroll
    for (int j = 0; j < 4; ++j) {
        float p = fmaxf(hsum2(acc[j][0]) + b4.x, 0.f) * a3.x +
                  fmaxf(hsum2(acc[j][1]) + b4.y, 0.f) * a3.y +
                  fmaxf(hsum2(acc[j][2]) + b4.z, 0.f) * a3.z +
                  fmaxf(hsum2(acc[j][3]) + b4.w, 0.f) * a3.w;
        #pragma unroll
        for (int off = 8; off >= 1; off >>= 1)
            p += __shfl_xor_sync(0xffffffffu, p, off);   // reduce over the 16 fslot lanes
        if (fslot == 0) {
            int it = islot + ISTR * j;
            g_logits[pn[it] * LL + pl[it]] = p + bA3;
        }
    }
}

// ---------------- post kernel: post = relu(content[pr_content] @ We + bWe) ----------------
#define LDIN 132   // padded stride for 128-col inputs (bank step 4)
#define LDACT 68   // padded stride for 64-col activations

struct SmemPost {
    float Wet[128 * 64];
    float bWe[64];
    float in[64 * LDIN];
    int   cix[64];
};

__global__ void __launch_bounds__(256, 1) k_post(
    const float* __restrict__ content, const float* __restrict__ Weg,
    const float* __restrict__ bWeg, const int* __restrict__ pr_content)
{
    extern __shared__ float smem_raw[];
    SmemPost& s = *(SmemPost*)smem_raw;
    int tid = threadIdx.x;
    load_wt(Weg, s.Wet, 128, tid, 256);
    if (tid < 64) { s.bWe[tid] = bWeg[tid]; s.cix[tid] = pr_content[blockIdx.x * 64 + tid]; }
    __syncthreads();
    for (int v = tid; v < 64 * 32; v += 256) {
        int it = v >> 5, sub = v & 31;
        *(float4*)(s.in + it * LDIN + sub * 4) =
            ((const float4*)(content + (size_t)s.cix[it] * 128))[sub];
    }
    __syncthreads();
    tile_gemm_p<16>(s.Wet, s.bWe, s.in, LDIN, 128,
                    g_post + (size_t)blockIdx.x * 64 * 64, 64, tid);
}

// ---------------- main kernel: 512 threads, 128-pair tiles ----------------
struct SmemMain {
    float W1t[128 * 64];
    float A1t[128 * 64];
    float W2t[64 * 64];
    float A2t[64 * 64];
    float b1[64], b2[64], bA1[64], bA2[64], A3[64];
    float in[128 * LDIN];    // [u|r], later [o|post]
    float act[128 * LDACT];  // x, later a1
    int pn[128], pl[128], uix[128], rix[128];
};

__global__ void __launch_bounds__(512, 1) k_main(
    const float* __restrict__ u2e, const float* __restrict__ r2e,
    const float* __restrict__ W1g, const float* __restrict__ b1g,
    const float* __restrict__ W2g, const float* __restrict__ b2g,
    const float* __restrict__ A1g, const float* __restrict__ bA1g,
    const float* __restrict__ A2g, const float* __restrict__ bA2g,
    const float* __restrict__ A3g, const float* __restrict__ bA3g,
    const int* __restrict__ pu, const int* __restrict__ pr)
{
    extern __shared__ float smem_raw[];
    SmemMain& s = *(SmemMain*)smem_raw;
    int tid = threadIdx.x;

    load_wt(W1g, s.W1t, 128, tid, 512);
    load_wt(A1g, s.A1t, 128, tid, 512);
    load_wt(W2g, s.W2t, 64, tid, 512);
    load_wt(A2g, s.A2t, 64, tid, 512);
    if (tid < 64) {
        s.b1[tid] = b1g[tid]; s.b2[tid] = b2g[tid];
        s.bA1[tid] = bA1g[tid]; s.bA2[tid] = bA2g[tid]; s.A3[tid] = A3g[tid];
    }
    float bA3 = bA3g[0];
    __syncthreads();

    int total = g_count;
    int ntiles = (total + 127) >> 7;

    for (int t = blockIdx.x; t < ntiles; t += gridDim.x) {
        int e0 = t << 7;
        if (tid < 128) {
            int e = e0 + tid;
            int pair = (e < total) ? g_pairs[e] : 0;   // pad -> (0,0), benign duplicate
            int n = pair >> 6, l = pair & 63;
            s.pn[tid] = n; s.pl[tid] = l;
            s.uix[tid] = pu[n * LL + l];
            s.rix[tid] = pr[n * LL + l];
        }
        __syncthreads();

        // gather [u;r] rows: 128 items x 32 float4
        for (int v = tid; v < 128 * 32; v += 512) {
            int it = v >> 5, sub = v & 31;
            float4 val;
            if (sub < 16) val = ((const float4*)(u2e + (size_t)s.uix[it] * 64))[sub];
            else          val = ((const float4*)(r2e + (size_t)s.rix[it] * 64))[sub - 16];
            *(float4*)(s.in + it * LDIN + sub * 4) = val;
        }
        __syncthreads();

        tile_gemm_p<32>(s.W1t, s.b1, s.in, LDIN, 128, s.act, LDACT, tid);  // x
        __syncthreads();
        // o = relu(x W2 + b2) -> in[:,0:64]; gather post -> in[:,64:128]
        tile_gemm_p<32>(s.W2t, s.b2, s.act, LDACT, 64, s.in, LDIN, tid);
        for (int v = tid; v < 128 * 16; v += 512) {
            int it = v >> 4, sub = v & 15;
            *(float4*)(s.in + it * LDIN + 64 + sub * 4) =
                ((const float4*)(g_post + s.pn[it] * 64))[sub];
        }
        __syncthreads();

        // write o to global (read by finalize); a1 = relu([o;post] A1 + bA1)
        for (int v = tid; v < 128 * 16; v += 512) {
            int it = v >> 4, sub = v & 15;
            ((float4*)(g_o + ((size_t)s.pn[it] * LL + s.pl[it]) * 64))[sub] =
                *(const float4*)(s.in + it * LDIN + sub * 4);
        }
        tile_gemm_p<32>(s.A1t, s.bA1, s.in, LDIN, 128, s.act, LDACT, tid);
        __syncthreads();
        tile_a2_logit_p<32>(s.A2t, s.bA2, s.act, LDACT, s.A3, bA3, s.pn, s.pl, tid);
        __syncthreads();   // protect pn/pl/in before next tile
    }
}

// ---------------- finalize: softmax + hist + output layer; 8 nodes per block-iter ----------
struct SmemFin {
    float Ow[128 * 64];
    float bOw[64];
    float att[8][64];
    float in[8][128];        // [hist | post]
    float red[8][4][64];
};

__global__ void __launch_bounds__(512, 1) k_fin(
    const float* __restrict__ Owg, const float* __restrict__ bOwg,
    const int* __restrict__ lengths, float* __restrict__ out)
{
    extern __shared__ float smem_raw[];
    SmemFin& s = *(SmemFin*)smem_raw;
    int tid = threadIdx.x;
    for (int i = tid; i < 128 * 64; i += 512) s.Ow[i] = Owg[i];
    if (tid < 64) s.bOw[tid] = bOwg[tid];
    __syncthreads();

    const int g = tid >> 6;          // node group 0..7
    const int gt = tid & 63;         // thread within group

    for (int base = blockIdx.x * 8; base < NN; base += gridDim.x * 8) {
        int n = base + g;
        int len = lengths[n];

        if (gt < 32) {
            int lane = gt;
            float l0 = (lane < len)      ? g_logits[n * LL + lane]      : -INFINITY;
            float l1 = (lane + 32 < len) ? g_logits[n * LL + lane + 32] : -INFINITY;
            float m = fmaxf(l0, l1);
            #pragma unroll
            for (int off = 16; off >= 1; off >>= 1)
                m = fmaxf(m, __shfl_xor_sync(0xffffffffu, m, off));
            float e0 = (lane < len)      ? expf(l0 - m) : 0.f;
            float e1 = (lane + 32 < len) ? expf(l1 - m) : 0.f;
            float sum = e0 + e1;
            #pragma unroll
            for (int off = 16; off >= 1; off >>= 1)
                sum += __shfl_xor_sync(0xffffffffu, sum, off);
            float inv = 1.f / sum;
            s.att[g][lane] = e0 * inv; s.att[g][lane + 32] = e1 * inv;
        } else {
            int f0 = gt - 32;
            s.in[g][64 + f0]      = g_post[n * 64 + f0];
            s.in[g][64 + f0 + 32] = g_post[n * 64 + f0 + 32];
        }
        __syncthreads();

        {
            float h = 0.f;
            const float* orow = g_o + (size_t)n * LL * 64 + gt;
            #pragma unroll 2
            for (int l = 0; l < len; ++l)
                h = fmaf(s.att[g][l], orow[(size_t)l * 64], h);
            s.in[g][gt] = h;
        }
        __syncthreads();

        {
            int fslot = gt & 15, kslot = gt >> 4;
            float4 acc = make_float4(0.f, 0.f, 0.f, 0.f);
            const float* Wp = s.Ow + fslot * 4;
            #pragma unroll 8
            for (int k = kslot * 32; k < kslot * 32 + 32; ++k) {
                float xv = s.in[g][k];
                float4 w = *(const float4*)(Wp + k * 64);
                acc.x = fmaf(xv, w.x, acc.x); acc.y = fmaf(xv, w.y, acc.y);
                acc.z = fmaf(xv, w.z, acc.z); acc.w = fmaf(xv, w.w, acc.w);
            }
            *(float4*)(&s.red[g][kslot][fslot * 4]) = acc;
        }
        __syncthreads();

        {
            float v = s.bOw[gt] + s.red[g][0][gt] + s.red[g][1][gt]
                                + s.red[g][2][gt] + s.red[g][3][gt];
            out[n * 64 + gt] = fmaxf(v, 0.f);
        }
        __syncthreads();
    }
}

// ---------------- launch ----------------
extern "C" void kernel_launch(void* const* d_in, const int* in_sizes, int n_in,
                              void* d_out, int out_size)
{
    const float* u2e     = (const float*)d_in[0];
    const float* r2e     = (const float*)d_in[1];
    const float* content = (const float*)d_in[2];
    const float* We_w = (const float*)d_in[3];  const float* We_b = (const float*)d_in[4];
    const float* W1_w = (const float*)d_in[5];  const float* W1_b = (const float*)d_in[6];
    const float* W2_w = (const float*)d_in[7];  const float* W2_b = (const float*)d_in[8];
    const float* A1_w = (const float*)d_in[9];  const float* A1_b = (const float*)d_in[10];
    const float* A2_w = (const float*)d_in[11]; const float* A2_b = (const float*)d_in[12];
    const float* A3_w = (const float*)d_in[13]; const float* A3_b = (const float*)d_in[14];
    const float* Ow_w = (const float*)d_in[15]; const float* Ow_b = (const float*)d_in[16];
    const int* pu      = (const int*)d_in[18];
    const int* pr      = (const int*)d_in[19];
    const int* lengths = (const int*)d_in[20];
    const int* prc     = (const int*)d_in[21];
    float* out = (float*)d_out;

    static int nsm = 0;
    if (nsm == 0) {
        cudaDeviceGetAttribute(&nsm, cudaDevAttrMultiProcessorCount, 0);
        cudaFuncSetAttribute(k_main, cudaFuncAttributeMaxDynamicSharedMemorySize, (int)sizeof(SmemMain));
        cudaFuncSetAttribute(k_post, cudaFuncAttributeMaxDynamicSharedMemorySize, (int)sizeof(SmemPost));
        cudaFuncSetAttribute(k_fin,  cudaFuncAttributeMaxDynamicSharedMemorySize, (int)sizeof(SmemFin));
    }

    k_reset<<<1, 1>>>();
    k_build_pairs<<<NN / 256, 256>>>(lengths);
    k_post<<<NN / 64, 256, sizeof(SmemPost)>>>(content, We_w, We_b, prc);
    k_main<<<nsm, 512, sizeof(SmemMain)>>>(u2e, r2e, W1_w, W1_b, W2_w, W2_b,
                                           A1_w, A1_b, A2_w, A2_b, A3_w, A3_b, pu, pr);
    k_fin<<<nsm, 512, sizeof(SmemFin)>>>(Ow_w, Ow_b, lengths, out);
}

// round 6
// speedup vs baseline: 1.4815x; 1.1485x over previous
#include <cuda_runtime.h>
#include <math.h>

#define NN 16384
#define LL 50
#define EE 64
#define CEDIM 128

typedef unsigned long long ull;

// ---------------- device scratch ----------------
__device__ float g_post[NN * EE];                    // 4 MB
__device__ float g_o[(size_t)NN * LL * EE];          // 210 MB
__device__ float g_logits[NN * LL];                  // 3.3 MB
__device__ int   g_pairs[NN * LL];                   // 3.3 MB
__device__ int   g_count;

__global__ void k_reset() { g_count = 0; }

__global__ void k_build_pairs(const int* __restrict__ lengths) {
    int n = blockIdx.x * blockDim.x + threadIdx.x;
    if (n >= NN) return;
    int len = lengths[n];
    int base = atomicAdd(&g_count, len);
    for (int l = 0; l < len; ++l) g_pairs[base + l] = (n << 6) | l;
}

// ---------------- packed f32x2 FMA ----------------
__device__ __forceinline__ void ffma2(ull& d, ull a, ull b) {
    asm("fma.rn.f32x2 %0, %1, %2, %0;" : "+l"(d) : "l"(a), "l"(b));
}
__device__ __forceinline__ float hsum2(ull v) {
    float2 p = *(float2*)&v;
    return p.x + p.y;
}

// Transposed-weight smem layout:
//   element (f, k) at float offset (k>>2)*256 + ((f>>2) + (f&3)*16)*4 + (k&3)
// Warp wfeat covers feats [wfeat*16, wfeat*16+16): its 4 fslot lanes read one
// contiguous 64B chunk per (kb, ff) -> 1 wavefront, conflict-free.
__device__ __forceinline__ void load_wt(const float* __restrict__ Wg, float* __restrict__ Wt,
                                        int K, int tid, int nthr) {
    for (int i = tid; i < K * 64; i += nthr) {
        int k = i >> 6, f = i & 63;
        Wt[(k >> 2) * 256 + ((f >> 2) + (f & 3) * 16) * 4 + (k & 3)] = Wg[i];
    }
}

// Lane/warp mapping: warp = 32 items x 16 feats.
//   fslot16 = (warp&3)*4 + (lane&3)   -> feat base F = fslot16*4
//   ibase   = (warp>>2)*32 + (lane>>2), items = ibase + 8*j, j<4
#define MAP_SLOTS() \
    const int fslot = (((tid >> 5) & 3) << 2) + (tid & 3); \
    const int ibase = ((tid >> 7) << 5) + ((tid >> 2) & 7);

// ---------------- packed tile GEMM ----------------
// out[i][f] = relu(bias[f] + sum_k in[i][k]*W[k][f])
__device__ __forceinline__ void tile_gemm_p(
    const float* __restrict__ Wt, const float* __restrict__ bias,
    const float* __restrict__ inA, int ldA, int K,
    float* __restrict__ out, int ldO, int tid)
{
    MAP_SLOTS();
    ull acc[4][4];
    #pragma unroll
    for (int j = 0; j < 4; ++j)
        #pragma unroll
        for (int ff = 0; ff < 4; ++ff) acc[j][ff] = 0ull;

    const float* wp = Wt + fslot * 4;
    const float* xp = inA + ibase * ldA;
    const int nkb = K >> 2;
    #pragma unroll 4
    for (int kb = 0; kb < nkb; ++kb) {
        ulonglong2 w[4];
        #pragma unroll
        for (int ff = 0; ff < 4; ++ff)
            w[ff] = *(const ulonglong2*)(wp + kb * 256 + ff * 64);
        ulonglong2 x[4];
        #pragma unroll
        for (int j = 0; j < 4; ++j)
            x[j] = *(const ulonglong2*)(xp + j * (8 * ldA) + kb * 4);
        #pragma unroll
        for (int j = 0; j < 4; ++j)
            #pragma unroll
            for (int ff = 0; ff < 4; ++ff) {
                ffma2(acc[j][ff], x[j].x, w[ff].x);
                ffma2(acc[j][ff], x[j].y, w[ff].y);
            }
    }
    float4 b4 = ((const float4*)bias)[fslot];
    #pragma unroll
    for (int j = 0; j < 4; ++j) {
        float4 v;
        v.x = fmaxf(hsum2(acc[j][0]) + b4.x, 0.f);
        v.y = fmaxf(hsum2(acc[j][1]) + b4.y, 0.f);
        v.z = fmaxf(hsum2(acc[j][2]) + b4.z, 0.f);
        v.w = fmaxf(hsum2(acc[j][3]) + b4.w, 0.f);
        *(float4*)(out + (ibase + 8 * j) * ldO + fslot * 4) = v;
    }
}

// A2 layer + A3 partial logit: a2 = relu(W*a1+b); per-warp partial of a2.A3
// reduced over the 4 fslot lanes of each islot group, written to red[wfeat][item].
__device__ __forceinline__ void tile_a2_logit_p(
    const float* __restrict__ Wt, const float* __restrict__ bias,
    const float* __restrict__ inA, int ldA,
    const float* __restrict__ A3,
    float* __restrict__ red,   // [4][128]
    int tid)
{
    MAP_SLOTS();
    const int wfeat = (tid >> 5) & 3;
    ull acc[4][4];
    #pragma unroll
    for (int j = 0; j < 4; ++j)
        #pragma unroll
        for (int ff = 0; ff < 4; ++ff) acc[j][ff] = 0ull;

    const float* wp = Wt + fslot * 4;
    const float* xp = inA + ibase * ldA;
    #pragma unroll 4
    for (int kb = 0; kb < 16; ++kb) {
        ulonglong2 w[4];
        #pragma unroll
        for (int ff = 0; ff < 4; ++ff)
            w[ff] = *(const ulonglong2*)(wp + kb * 256 + ff * 64);
        ulonglong2 x[4];
        #pragma unroll
        for (int j = 0; j < 4; ++j)
            x[j] = *(const ulonglong2*)(xp + j * (8 * ldA) + kb * 4);
        #pragma unroll
        for (int j = 0; j < 4; ++j)
            #pragma unroll
            for (int ff = 0; ff < 4; ++ff) {
                ffma2(acc[j][ff], x[j].x, w[ff].x);
                ffma2(acc[j][ff], x[j].y, w[ff].y);
            }
    }
    float4 b4 = ((const float4*)bias)[fslot];
    float4 a3 = ((const float4*)A3)[fslot];
    #pragma unroll
    for (int j = 0; j < 4; ++j) {
        float p = fmaxf(hsum2(acc[j][0]) + b4.x, 0.f) * a3.x +
                  fmaxf(hsum2(acc[j][1]) + b4.y, 0.f) * a3.y +
                  fmaxf(hsum2(acc[j][2]) + b4.z, 0.f) * a3.z +
                  fmaxf(hsum2(acc[j][3]) + b4.w, 0.f) * a3.w;
        p += __shfl_xor_sync(0xffffffffu, p, 1);
        p += __shfl_xor_sync(0xffffffffu, p, 2);   // sum over 4 fslot lanes
        if ((tid & 3) == 0)
            red[wfeat * 128 + ibase + 8 * j] = p;
    }
}

// ---------------- post kernel: post = relu(content[pr_content] @ We + bWe) ----------------
#define LDIN 132   // padded stride for 128-col inputs (bank step 4)
#define LDACT 68   // padded stride for 64-col activations

struct SmemPost {
    float Wet[128 * 64];
    float bWe[64];
    float in[64 * LDIN];
    int   cix[64];
};

__global__ void __launch_bounds__(256, 1) k_post(
    const float* __restrict__ content, const float* __restrict__ Weg,
    const float* __restrict__ bWeg, const int* __restrict__ pr_content)
{
    extern __shared__ float smem_raw[];
    SmemPost& s = *(SmemPost*)smem_raw;
    int tid = threadIdx.x;
    load_wt(Weg, s.Wet, 128, tid, 256);
    if (tid < 64) { s.bWe[tid] = bWeg[tid]; s.cix[tid] = pr_content[blockIdx.x * 64 + tid]; }
    __syncthreads();
    for (int v = tid; v < 64 * 32; v += 256) {
        int it = v >> 5, sub = v & 31;
        *(float4*)(s.in + it * LDIN + sub * 4) =
            ((const float4*)(content + (size_t)s.cix[it] * 128))[sub];
    }
    __syncthreads();
    tile_gemm_p(s.Wet, s.bWe, s.in, LDIN, 128,
                g_post + (size_t)blockIdx.x * 64 * 64, 64, tid);
}

// ---------------- main kernel: 512 threads, 128-pair tiles ----------------
struct SmemMain {
    float W1t[128 * 64];
    float A1t[128 * 64];
    float W2t[64 * 64];
    float A2t[64 * 64];
    float b1[64], b2[64], bA1[64], bA2[64], A3[64];
    float in[128 * LDIN];    // [u|r], later [o|post]
    float act[128 * LDACT];  // x, later a1
    float red[4 * 128];      // logit partials per wfeat
    int pn[128], pl[128], uix[128], rix[128];
};

__global__ void __launch_bounds__(512, 1) k_main(
    const float* __restrict__ u2e, const float* __restrict__ r2e,
    const float* __restrict__ W1g, const float* __restrict__ b1g,
    const float* __restrict__ W2g, const float* __restrict__ b2g,
    const float* __restrict__ A1g, const float* __restrict__ bA1g,
    const float* __restrict__ A2g, const float* __restrict__ bA2g,
    const float* __restrict__ A3g, const float* __restrict__ bA3g,
    const int* __restrict__ pu, const int* __restrict__ pr)
{
    extern __shared__ float smem_raw[];
    SmemMain& s = *(SmemMain*)smem_raw;
    int tid = threadIdx.x;

    load_wt(W1g, s.W1t, 128, tid, 512);
    load_wt(A1g, s.A1t, 128, tid, 512);
    load_wt(W2g, s.W2t, 64, tid, 512);
    load_wt(A2g, s.A2t, 64, tid, 512);
    if (tid < 64) {
        s.b1[tid] = b1g[tid]; s.b2[tid] = b2g[tid];
        s.bA1[tid] = bA1g[tid]; s.bA2[tid] = bA2g[tid]; s.A3[tid] = A3g[tid];
    }
    float bA3 = bA3g[0];
    __syncthreads();

    int total = g_count;
    int ntiles = (total + 127) >> 7;

    for (int t = blockIdx.x; t < ntiles; t += gridDim.x) {
        int e0 = t << 7;
        if (tid < 128) {
            int e = e0 + tid;
            int pair = (e < total) ? g_pairs[e] : 0;   // pad -> (0,0), benign duplicate
            int n = pair >> 6, l = pair & 63;
            s.pn[tid] = n; s.pl[tid] = l;
            s.uix[tid] = pu[n * LL + l];
            s.rix[tid] = pr[n * LL + l];
        }
        __syncthreads();

        // gather [u;r] rows: 128 items x 32 float4
        for (int v = tid; v < 128 * 32; v += 512) {
            int it = v >> 5, sub = v & 31;
            float4 val;
            if (sub < 16) val = ((const float4*)(u2e + (size_t)s.uix[it] * 64))[sub];
            else          val = ((const float4*)(r2e + (size_t)s.rix[it] * 64))[sub - 16];
            *(float4*)(s.in + it * LDIN + sub * 4) = val;
        }
        __syncthreads();

        tile_gemm_p(s.W1t, s.b1, s.in, LDIN, 128, s.act, LDACT, tid);  // x
        __syncthreads();
        // o = relu(x W2 + b2) -> in[:,0:64]; gather post -> in[:,64:128]
        tile_gemm_p(s.W2t, s.b2, s.act, LDACT, 64, s.in, LDIN, tid);
        for (int v = tid; v < 128 * 16; v += 512) {
            int it = v >> 4, sub = v & 15;
            *(float4*)(s.in + it * LDIN + 64 + sub * 4) =
                ((const float4*)(g_post + s.pn[it] * 64))[sub];
        }
        __syncthreads();

        // write o to global (read by finalize); a1 = relu([o;post] A1 + bA1)
        for (int v = tid; v < 128 * 16; v += 512) {
            int it = v >> 4, sub = v & 15;
            ((float4*)(g_o + ((size_t)s.pn[it] * LL + s.pl[it]) * 64))[sub] =
                *(const float4*)(s.in + it * LDIN + sub * 4);
        }
        tile_gemm_p(s.A1t, s.bA1, s.in, LDIN, 128, s.act, LDACT, tid);
        __syncthreads();
        tile_a2_logit_p(s.A2t, s.bA2, s.act, LDACT, s.A3, s.red, tid);
        __syncthreads();
        if (tid < 128) {
            float lg = s.red[tid] + s.red[128 + tid] + s.red[256 + tid] + s.red[384 + tid];
            g_logits[s.pn[tid] * LL + s.pl[tid]] = lg + bA3;
        }
        __syncthreads();   // protect pn/pl/in/red before next tile
    }
}

// ---------------- finalize: softmax + hist + output layer; 8 nodes per block-iter ----------
struct SmemFin {
    float Ow[128 * 64];
    float bOw[64];
    float att[8][64];
    float in[8][128];        // [hist | post]
    float red[8][4][64];
};

__global__ void __launch_bounds__(512, 1) k_fin(
    const float* __restrict__ Owg, const float* __restrict__ bOwg,
    const int* __restrict__ lengths, float* __restrict__ out)
{
    extern __shared__ float smem_raw[];
    SmemFin& s = *(SmemFin*)smem_raw;
    int tid = threadIdx.x;
    for (int i = tid; i < 128 * 64; i += 512) s.Ow[i] = Owg[i];
    if (tid < 64) s.bOw[tid] = bOwg[tid];
    __syncthreads();

    const int g = tid >> 6;          // node group 0..7
    const int gt = tid & 63;         // thread within group

    for (int base = blockIdx.x * 8; base < NN; base += gridDim.x * 8) {
        int n = base + g;
        int len = lengths[n];

        if (gt < 32) {
            int lane = gt;
            float l0 = (lane < len)      ? g_logits[n * LL + lane]      : -INFINITY;
            float l1 = (lane + 32 < len) ? g_logits[n * LL + lane + 32] : -INFINITY;
            float m = fmaxf(l0, l1);
            #pragma unroll
            for (int off = 16; off >= 1; off >>= 1)
                m = fmaxf(m, __shfl_xor_sync(0xffffffffu, m, off));
            float e0 = (lane < len)      ? expf(l0 - m) : 0.f;
            float e1 = (lane + 32 < len) ? expf(l1 - m) : 0.f;
            float sum = e0 + e1;
            #pragma unroll
            for (int off = 16; off >= 1; off >>= 1)
                sum += __shfl_xor_sync(0xffffffffu, sum, off);
            float inv = 1.f / sum;
            s.att[g][lane] = e0 * inv; s.att[g][lane + 32] = e1 * inv;
        } else {
            int f0 = gt - 32;
            s.in[g][64 + f0]      = g_post[n * 64 + f0];
            s.in[g][64 + f0 + 32] = g_post[n * 64 + f0 + 32];
        }
        __syncthreads();

        // hist[f] = sum_l att[l]*o[n][l][f] with 4 independent accumulators (MLP=4)
        {
            const float* orow = g_o + (size_t)n * LL * 64 + gt;
            float h0 = 0.f, h1 = 0.f, h2 = 0.f, h3 = 0.f;
            int l = 0;
            for (; l + 3 < len; l += 4) {
                h0 = fmaf(s.att[g][l],     orow[(size_t)(l)     * 64], h0);
                h1 = fmaf(s.att[g][l + 1], orow[(size_t)(l + 1) * 64], h1);
                h2 = fmaf(s.att[g][l + 2], orow[(size_t)(l + 2) * 64], h2);
                h3 = fmaf(s.att[g][l + 3], orow[(size_t)(l + 3) * 64], h3);
            }
            for (; l < len; ++l)
                h0 = fmaf(s.att[g][l], orow[(size_t)l * 64], h0);
            s.in[g][gt] = (h0 + h1) + (h2 + h3);
        }
        __syncthreads();

        {
            int fslot = gt & 15, kslot = gt >> 4;
            float4 acc = make_float4(0.f, 0.f, 0.f, 0.f);
            const float* Wp = s.Ow + fslot * 4;
            #pragma unroll 8
            for (int k = kslot * 32; k < kslot * 32 + 32; ++k) {
                float xv = s.in[g][k];
                float4 w = *(const float4*)(Wp + k * 64);
                acc.x = fmaf(xv, w.x, acc.x); acc.y = fmaf(xv, w.y, acc.y);
                acc.z = fmaf(xv, w.z, acc.z); acc.w = fmaf(xv, w.w, acc.w);
            }
            *(float4*)(&s.red[g][kslot][fslot * 4]) = acc;
        }
        __syncthreads();

        {
            float v = s.bOw[gt] + s.red[g][0][gt] + s.red[g][1][gt]
                                + s.red[g][2][gt] + s.red[g][3][gt];
            out[n * 64 + gt] = fmaxf(v, 0.f);
        }
        __syncthreads();
    }
}

// ---------------- launch ----------------
extern "C" void kernel_launch(void* const* d_in, const int* in_sizes, int n_in,
                              void* d_out, int out_size)
{
    const float* u2e     = (const float*)d_in[0];
    const float* r2e     = (const float*)d_in[1];
    const float* content = (const float*)d_in[2];
    const float* We_w = (const float*)d_in[3];  const float* We_b = (const float*)d_in[4];
    const float* W1_w = (const float*)d_in[5];  const float* W1_b = (const float*)d_in[6];
    const float* W2_w = (const float*)d_in[7];  const float* W2_b = (const float*)d_in[8];
    const float* A1_w = (const float*)d_in[9];  const float* A1_b = (const float*)d_in[10];
    const float* A2_w = (const float*)d_in[11]; const float* A2_b = (const float*)d_in[12];
    const float* A3_w = (const float*)d_in[13]; const float* A3_b = (const float*)d_in[14];
    const float* Ow_w = (const float*)d_in[15]; const float* Ow_b = (const float*)d_in[16];
    const int* pu      = (const int*)d_in[18];
    const int* pr      = (const int*)d_in[19];
    const int* lengths = (const int*)d_in[20];
    const int* prc     = (const int*)d_in[21];
    float* out = (float*)d_out;

    static int nsm = 0;
    if (nsm == 0) {
        cudaDeviceGetAttribute(&nsm, cudaDevAttrMultiProcessorCount, 0);
        cudaFuncSetAttribute(k_main, cudaFuncAttributeMaxDynamicSharedMemorySize, (int)sizeof(SmemMain));
        cudaFuncSetAttribute(k_post, cudaFuncAttributeMaxDynamicSharedMemorySize, (int)sizeof(SmemPost));
        cudaFuncSetAttribute(k_fin,  cudaFuncAttributeMaxDynamicSharedMemorySize, (int)sizeof(SmemFin));
    }

    k_reset<<<1, 1>>>();
    k_build_pairs<<<NN / 256, 256>>>(lengths);
    k_post<<<NN / 64, 256, sizeof(SmemPost)>>>(content, We_w, We_b, prc);
    k_main<<<nsm, 512, sizeof(SmemMain)>>>(u2e, r2e, W1_w, W1_b, W2_w, W2_b,
                                           A1_w, A1_b, A2_w, A2_b, A3_w, A3_b, pu, pr);
    k_fin<<<nsm, 512, sizeof(SmemFin)>>>(Ow_w, Ow_b, lengths, out);
}

// round 7
// speedup vs baseline: 1.6406x; 1.1074x over previous
#include <cuda_runtime.h>
#include <math.h>

#define NN 16384
#define LL 50
#define EE 64
#define CEDIM 128

typedef unsigned long long ull;

// ---------------- device scratch ----------------
__device__ float g_post[NN * EE];                    // 4 MB
__device__ float g_o[(size_t)NN * LL * EE];          // 210 MB
__device__ float g_logits[NN * LL];                  // 3.3 MB
__device__ int   g_pairs[NN * LL];                   // 3.3 MB
__device__ int   g_count;

__global__ void k_reset() { g_count = 0; }

__global__ void k_build_pairs(const int* __restrict__ lengths) {
    int n = blockIdx.x * blockDim.x + threadIdx.x;
    if (n >= NN) return;
    int len = lengths[n];
    int base = atomicAdd(&g_count, len);
    for (int l = 0; l < len; ++l) g_pairs[base + l] = (n << 6) | l;
}

// ---------------- packed f32x2 FMA + cp.async ----------------
__device__ __forceinline__ void ffma2(ull& d, ull a, ull b) {
    asm("fma.rn.f32x2 %0, %1, %2, %0;" : "+l"(d) : "l"(a), "l"(b));
}
__device__ __forceinline__ float hsum2(ull v) {
    float2 p = *(float2*)&v;
    return p.x + p.y;
}
__device__ __forceinline__ void cp16(void* dst, const void* src) {
    unsigned d = (unsigned)__cvta_generic_to_shared(dst);
    asm volatile("cp.async.cg.shared.global [%0], [%1], 16;" :: "r"(d), "l"(src));
}
__device__ __forceinline__ void cp_commit() {
    asm volatile("cp.async.commit_group;");
}
__device__ __forceinline__ void cp_wait0() {
    asm volatile("cp.async.wait_group 0;" ::: "memory");
}
__device__ __forceinline__ void barh(int half) {
    asm volatile("bar.sync %0, 256;" :: "r"(half + 1) : "memory");
}

// Transposed-weight smem layout:
//   element (f, k) at float offset (k>>2)*256 + ((f>>2) + (f&3)*16)*4 + (k&3)
// Warp wfeat covers feats [wfeat*16, wfeat*16+16): its 4 fslot lanes read one
// contiguous 64B chunk per (kb, ff) -> 1 wavefront, conflict-free.
__device__ __forceinline__ void load_wt(const float* __restrict__ Wg, float* __restrict__ Wt,
                                        int K, int tid, int nthr) {
    for (int i = tid; i < K * 64; i += nthr) {
        int k = i >> 6, f = i & 63;
        Wt[(k >> 2) * 256 + ((f >> 2) + (f & 3) * 16) * 4 + (k & 3)] = Wg[i];
    }
}

// Lane/warp mapping within a 256-thread half: warp = 32 items x 16 feats.
//   fslot16 = (warp&3)*4 + (lane&3) -> feat base F = fslot16*4
//   ibase   = (htid>>7)*32 + (lane>>2), items = ibase + 8*j, j<4  (64-item tile)
#define MAP_SLOTS() \
    const int fslot = (((tid >> 5) & 3) << 2) + (tid & 3); \
    const int ibase = ((tid >> 7) << 5) + ((tid >> 2) & 7);

// ---------------- packed tile GEMM (64 items x 64 feats per 256-thread half) --------
__device__ __forceinline__ void tile_gemm_p(
    const float* __restrict__ Wt, const float* __restrict__ bias,
    const float* __restrict__ inA, int ldA, int K,
    float* __restrict__ out, int ldO, int tid)
{
    MAP_SLOTS();
    ull acc[4][4];
    #pragma unroll
    for (int j = 0; j < 4; ++j)
        #pragma unroll
        for (int ff = 0; ff < 4; ++ff) acc[j][ff] = 0ull;

    const float* wp = Wt + fslot * 4;
    const float* xp = inA + ibase * ldA;
    const int nkb = K >> 2;
    #pragma unroll 4
    for (int kb = 0; kb < nkb; ++kb) {
        ulonglong2 w[4];
        #pragma unroll
        for (int ff = 0; ff < 4; ++ff)
            w[ff] = *(const ulonglong2*)(wp + kb * 256 + ff * 64);
        ulonglong2 x[4];
        #pragma unroll
        for (int j = 0; j < 4; ++j)
            x[j] = *(const ulonglong2*)(xp + j * (8 * ldA) + kb * 4);
        #pragma unroll
        for (int j = 0; j < 4; ++j)
            #pragma unroll
            for (int ff = 0; ff < 4; ++ff) {
                ffma2(acc[j][ff], x[j].x, w[ff].x);
                ffma2(acc[j][ff], x[j].y, w[ff].y);
            }
    }
    float4 b4 = ((const float4*)bias)[fslot];
    #pragma unroll
    for (int j = 0; j < 4; ++j) {
        float4 v;
        v.x = fmaxf(hsum2(acc[j][0]) + b4.x, 0.f);
        v.y = fmaxf(hsum2(acc[j][1]) + b4.y, 0.f);
        v.z = fmaxf(hsum2(acc[j][2]) + b4.z, 0.f);
        v.w = fmaxf(hsum2(acc[j][3]) + b4.w, 0.f);
        *(float4*)(out + (ibase + 8 * j) * ldO + fslot * 4) = v;
    }
}

// A2 layer + A3 partial logit: per-warp partial of a2.A3 into red[wfeat][item]
__device__ __forceinline__ void tile_a2_logit_p(
    const float* __restrict__ Wt, const float* __restrict__ bias,
    const float* __restrict__ inA, int ldA,
    const float* __restrict__ A3,
    float* __restrict__ red,   // [4][64]
    int tid)
{
    MAP_SLOTS();
    const int wfeat = (tid >> 5) & 3;
    ull acc[4][4];
    #pragma unroll
    for (int j = 0; j < 4; ++j)
        #pragma unroll
        for (int ff = 0; ff < 4; ++ff) acc[j][ff] = 0ull;

    const float* wp = Wt + fslot * 4;
    const float* xp = inA + ibase * ldA;
    #pragma unroll 4
    for (int kb = 0; kb < 16; ++kb) {
        ulonglong2 w[4];
        #pragma unroll
        for (int ff = 0; ff < 4; ++ff)
            w[ff] = *(const ulonglong2*)(wp + kb * 256 + ff * 64);
        ulonglong2 x[4];
        #pragma unroll
        for (int j = 0; j < 4; ++j)
            x[j] = *(const ulonglong2*)(xp + j * (8 * ldA) + kb * 4);
        #pragma unroll
        for (int j = 0; j < 4; ++j)
            #pragma unroll
            for (int ff = 0; ff < 4; ++ff) {
                ffma2(acc[j][ff], x[j].x, w[ff].x);
                ffma2(acc[j][ff], x[j].y, w[ff].y);
            }
    }
    float4 b4 = ((const float4*)bias)[fslot];
    float4 a3 = ((const float4*)A3)[fslot];
    #pragma unroll
    for (int j = 0; j < 4; ++j) {
        float p = fmaxf(hsum2(acc[j][0]) + b4.x, 0.f) * a3.x +
                  fmaxf(hsum2(acc[j][1]) + b4.y, 0.f) * a3.y +
                  fmaxf(hsum2(acc[j][2]) + b4.z, 0.f) * a3.z +
                  fmaxf(hsum2(acc[j][3]) + b4.w, 0.f) * a3.w;
        p += __shfl_xor_sync(0xffffffffu, p, 1);
        p += __shfl_xor_sync(0xffffffffu, p, 2);   // sum over 4 fslot lanes
        if ((tid & 3) == 0)
            red[wfeat * 64 + ibase + 8 * j] = p;
    }
}

// ---------------- post kernel: post = relu(content[pr_content] @ We + bWe) ----------------
#define LDIN 132   // padded stride for 128-col inputs (bank step 4)
#define LDACT 68   // padded stride for 64-col activations

struct SmemPost {
    float Wet[128 * 64];
    float bWe[64];
    float in[64 * LDIN];
    int   cix[64];
};

// k_post uses the OLD 512-wide mapping trick: run as one 256-thread block but the
// MAP_SLOTS ibase formula needs tid>>7 in {0,1}: with 256 threads, tid>>7 covers
// {0,1} -> 64 items. Works unchanged.
__global__ void __launch_bounds__(256, 1) k_post(
    const float* __restrict__ content, const float* __restrict__ Weg,
    const float* __restrict__ bWeg, const int* __restrict__ pr_content)
{
    extern __shared__ float smem_raw[];
    SmemPost& s = *(SmemPost*)smem_raw;
    int tid = threadIdx.x;
    load_wt(Weg, s.Wet, 128, tid, 256);
    if (tid < 64) { s.bWe[tid] = bWeg[tid]; s.cix[tid] = pr_content[blockIdx.x * 64 + tid]; }
    __syncthreads();
    for (int v = tid; v < 64 * 32; v += 256) {
        int it = v >> 5, sub = v & 31;
        cp16(s.in + it * LDIN + sub * 4,
             content + (size_t)s.cix[it] * 128 + sub * 4);
    }
    cp_commit(); cp_wait0();
    __syncthreads();
    tile_gemm_p(s.Wet, s.bWe, s.in, LDIN, 128,
                g_post + (size_t)blockIdx.x * 64 * 64, 64, tid);
}

// ---------------- main kernel: 2 independent 256-thread halves, 64-pair tiles --------
struct SmemHalf {
    float in[64 * LDIN];     // [u|r], later [o|post]
    float act[64 * LDACT];   // x, later a1
    float red[4 * 64];
    int pn[64], pl[64], uix[64], rix[64];
};
struct SmemMain {
    float W1t[128 * 64];
    float A1t[128 * 64];
    float W2t[64 * 64];
    float A2t[64 * 64];
    float b1[64], b2[64], bA1[64], bA2[64], A3[64];
    SmemHalf h[2];
};

__global__ void __launch_bounds__(512, 1) k_main(
    const float* __restrict__ u2e, const float* __restrict__ r2e,
    const float* __restrict__ W1g, const float* __restrict__ b1g,
    const float* __restrict__ W2g, const float* __restrict__ b2g,
    const float* __restrict__ A1g, const float* __restrict__ bA1g,
    const float* __restrict__ A2g, const float* __restrict__ bA2g,
    const float* __restrict__ A3g, const float* __restrict__ bA3g,
    const int* __restrict__ pu, const int* __restrict__ pr)
{
    extern __shared__ float smem_raw[];
    SmemMain& s = *(SmemMain*)smem_raw;
    int tid = threadIdx.x;

    load_wt(W1g, s.W1t, 128, tid, 512);
    load_wt(A1g, s.A1t, 128, tid, 512);
    load_wt(W2g, s.W2t, 64, tid, 512);
    load_wt(A2g, s.A2t, 64, tid, 512);
    if (tid < 64) {
        s.b1[tid] = b1g[tid]; s.b2[tid] = b2g[tid];
        s.bA1[tid] = bA1g[tid]; s.bA2[tid] = bA2g[tid]; s.A3[tid] = A3g[tid];
    }
    float bA3 = bA3g[0];
    __syncthreads();

    const int half = tid >> 8;       // 0 or 1
    const int htid = tid & 255;
    SmemHalf& h = s.h[half];

    int total = g_count;
    int ntiles = (total + 63) >> 6;

    for (int t = blockIdx.x * 2 + half; t < ntiles; t += gridDim.x * 2) {
        int e0 = t << 6;
        if (htid < 64) {
            int e = e0 + htid;
            int pair = (e < total) ? g_pairs[e] : 0;   // pad -> (0,0), benign duplicate
            int n = pair >> 6, l = pair & 63;
            h.pn[htid] = n; h.pl[htid] = l;
            h.uix[htid] = pu[n * LL + l];
            h.rix[htid] = pr[n * LL + l];
        }
        barh(half);

        // gather [u;r] rows via cp.async: 64 items x 32 16B chunks
        for (int v = htid; v < 64 * 32; v += 256) {
            int it = v >> 5, sub = v & 31;
            const float* src = (sub < 16)
                ? u2e + (size_t)h.uix[it] * 64 + sub * 4
                : r2e + (size_t)h.rix[it] * 64 + (sub - 16) * 4;
            cp16(h.in + it * LDIN + sub * 4, src);
        }
        cp_commit(); cp_wait0();
        barh(half);

        tile_gemm_p(s.W1t, s.b1, h.in, LDIN, 128, h.act, LDACT, htid);   // x
        barh(half);

        // post gather (async, overlaps W2) + o = relu(x W2 + b2) -> in[:,0:64]
        for (int v = htid; v < 64 * 16; v += 256) {
            int it = v >> 4, sub = v & 15;
            cp16(h.in + it * LDIN + 64 + sub * 4, g_post + h.pn[it] * 64 + sub * 4);
        }
        cp_commit();
        tile_gemm_p(s.W2t, s.b2, h.act, LDACT, 64, h.in, LDIN, htid);
        cp_wait0();
        barh(half);

        // o-write (fire-and-forget STG) overlaps A1 GEMM (both read h.in)
        for (int v = htid; v < 64 * 16; v += 256) {
            int it = v >> 4, sub = v & 15;
            ((float4*)(g_o + ((size_t)h.pn[it] * LL + h.pl[it]) * 64))[sub] =
                *(const float4*)(h.in + it * LDIN + sub * 4);
        }
        tile_gemm_p(s.A1t, s.bA1, h.in, LDIN, 128, h.act, LDACT, htid);  // a1
        barh(half);

        tile_a2_logit_p(s.A2t, s.bA2, h.act, LDACT, s.A3, h.red, htid);
        barh(half);

        if (htid < 64) {
            float lg = h.red[htid] + h.red[64 + htid] + h.red[128 + htid] + h.red[192 + htid];
            g_logits[h.pn[htid] * LL + h.pl[htid]] = lg + bA3;
        }
        barh(half);   // protect pn/pl/in/red before next tile
    }
}

// ---------------- finalize: softmax + hist + output layer; 8 nodes per block-iter ----------
struct SmemFin {
    float Ow[128 * 64];
    float bOw[64];
    float att[8][64];
    float in[8][128];        // [hist | post]
    float red[8][4][64];
};

__global__ void __launch_bounds__(512, 1) k_fin(
    const float* __restrict__ Owg, const float* __restrict__ bOwg,
    const int* __restrict__ lengths, float* __restrict__ out)
{
    extern __shared__ float smem_raw[];
    SmemFin& s = *(SmemFin*)smem_raw;
    int tid = threadIdx.x;
    for (int i = tid; i < 128 * 64; i += 512) s.Ow[i] = Owg[i];
    if (tid < 64) s.bOw[tid] = bOwg[tid];
    __syncthreads();

    const int g = tid >> 6;          // node group 0..7
    const int gt = tid & 63;         // thread within group

    for (int base = blockIdx.x * 8; base < NN; base += gridDim.x * 8) {
        int n = base + g;
        int len = lengths[n];

        if (gt < 32) {
            int lane = gt;
            float l0 = (lane < len)      ? g_logits[n * LL + lane]      : -INFINITY;
            float l1 = (lane + 32 < len) ? g_logits[n * LL + lane + 32] : -INFINITY;
            float m = fmaxf(l0, l1);
            #pragma unroll
            for (int off = 16; off >= 1; off >>= 1)
                m = fmaxf(m, __shfl_xor_sync(0xffffffffu, m, off));
            float e0 = (lane < len)      ? expf(l0 - m) : 0.f;
            float e1 = (lane + 32 < len) ? expf(l1 - m) : 0.f;
            float sum = e0 + e1;
            #pragma unroll
            for (int off = 16; off >= 1; off >>= 1)
                sum += __shfl_xor_sync(0xffffffffu, sum, off);
            float inv = 1.f / sum;
            s.att[g][lane] = e0 * inv; s.att[g][lane + 32] = e1 * inv;
        } else {
            int f0 = gt - 32;
            s.in[g][64 + f0]      = g_post[n * 64 + f0];
            s.in[g][64 + f0 + 32] = g_post[n * 64 + f0 + 32];
        }
        __syncthreads();

        // hist[f] = sum_l att[l]*o[n][l][f] with 4 independent accumulators
        {
            const float* orow = g_o + (size_t)n * LL * 64 + gt;
            float h0 = 0.f, h1 = 0.f, h2 = 0.f, h3 = 0.f;
            int l = 0;
            for (; l + 3 < len; l += 4) {
                h0 = fmaf(s.att[g][l],     orow[(size_t)(l)     * 64], h0);
                h1 = fmaf(s.att[g][l + 1], orow[(size_t)(l + 1) * 64], h1);
                h2 = fmaf(s.att[g][l + 2], orow[(size_t)(l + 2) * 64], h2);
                h3 = fmaf(s.att[g][l + 3], orow[(size_t)(l + 3) * 64], h3);
            }
            for (; l < len; ++l)
                h0 = fmaf(s.att[g][l], orow[(size_t)l * 64], h0);
            s.in[g][gt] = (h0 + h1) + (h2 + h3);
        }
        __syncthreads();

        {
            int fslot = gt & 15, kslot = gt >> 4;
            float4 acc = make_float4(0.f, 0.f, 0.f, 0.f);
            const float* Wp = s.Ow + fslot * 4;
            #pragma unroll 8
            for (int k = kslot * 32; k < kslot * 32 + 32; ++k) {
                float xv = s.in[g][k];
                float4 w = *(const float4*)(Wp + k * 64);
                acc.x = fmaf(xv, w.x, acc.x); acc.y = fmaf(xv, w.y, acc.y);
                acc.z = fmaf(xv, w.z, acc.z); acc.w = fmaf(xv, w.w, acc.w);
            }
            *(float4*)(&s.red[g][kslot][fslot * 4]) = acc;
        }
        __syncthreads();

        {
            float v = s.bOw[gt] + s.red[g][0][gt] + s.red[g][1][gt]
                                + s.red[g][2][gt] + s.red[g][3][gt];
            out[n * 64 + gt] = fmaxf(v, 0.f);
        }
        __syncthreads();
    }
}

// ---------------- launch ----------------
extern "C" void kernel_launch(void* const* d_in, const int* in_sizes, int n_in,
                              void* d_out, int out_size)
{
    const float* u2e     = (const float*)d_in[0];
    const float* r2e     = (const float*)d_in[1];
    const float* content = (const float*)d_in[2];
    const float* We_w = (const float*)d_in[3];  const float* We_b = (const float*)d_in[4];
    const float* W1_w = (const float*)d_in[5];  const float* W1_b = (const float*)d_in[6];
    const float* W2_w = (const float*)d_in[7];  const float* W2_b = (const float*)d_in[8];
    const float* A1_w = (const float*)d_in[9];  const float* A1_b = (const float*)d_in[10];
    const float* A2_w = (const float*)d_in[11]; const float* A2_b = (const float*)d_in[12];
    const float* A3_w = (const float*)d_in[13]; const float* A3_b = (const float*)d_in[14];
    const float* Ow_w = (const float*)d_in[15]; const float* Ow_b = (const float*)d_in[16];
    const int* pu      = (const int*)d_in[18];
    const int* pr      = (const int*)d_in[19];
    const int* lengths = (const int*)d_in[20];
    const int* prc     = (const int*)d_in[21];
    float* out = (float*)d_out;

    static int nsm = 0;
    if (nsm == 0) {
        cudaDeviceGetAttribute(&nsm, cudaDevAttrMultiProcessorCount, 0);
        cudaFuncSetAttribute(k_main, cudaFuncAttributeMaxDynamicSharedMemorySize, (int)sizeof(SmemMain));
        cudaFuncSetAttribute(k_post, cudaFuncAttributeMaxDynamicSharedMemorySize, (int)sizeof(SmemPost));
        cudaFuncSetAttribute(k_fin,  cudaFuncAttributeMaxDynamicSharedMemorySize, (int)sizeof(SmemFin));
    }

    k_reset<<<1, 1>>>();
    k_build_pairs<<<NN / 256, 256>>>(lengths);
    k_post<<<NN / 64, 256, sizeof(SmemPost)>>>(content, We_w, We_b, prc);
    k_main<<<nsm, 512, sizeof(SmemMain)>>>(u2e, r2e, W1_w, W1_b, W2_w, W2_b,
                                           A1_w, A1_b, A2_w, A2_b, A3_w, A3_b, pu, pr);
    k_fin<<<nsm, 512, sizeof(SmemFin)>>>(Ow_w, Ow_b, lengths, out);
}

// round 10
// speedup vs baseline: 1.9667x; 1.1988x over previous
#include <cuda_runtime.h>
#include <cuda_bf16.h>
#include <mma.h>
#include <cstdint>
#include <math.h>

#define NN 16384
#define LL 50
#define EE 64
#define CEDIM 128
#define NUSERS 100000
#define NRAT 6

typedef unsigned long long ull;
typedef unsigned int u32;

using namespace nvcuda;
typedef wmma::fragment<wmma::matrix_a, 16, 16, 16, __nv_bfloat16, wmma::row_major> FragA;
typedef wmma::fragment<wmma::matrix_b, 16, 16, 16, __nv_bfloat16, wmma::row_major> FragB;
typedef wmma::fragment<wmma::accumulator, 16, 16, 16, float> FragC;

// ---------------- device scratch ----------------
__device__ float g_post[NN * EE];                    // 4 MB
__device__ float g_o[(size_t)NN * LL * EE];          // 210 MB
__device__ float g_logits[NN * LL];                  // 3.3 MB
__device__ int   g_pairs[NN * LL];                   // 3.3 MB
__device__ int   g_count;
// packed hi/lo bf16 tables
__device__ __nv_bfloat16 g_u2e_h[NUSERS * EE];
__device__ __nv_bfloat16 g_u2e_l[NUSERS * EE];
__device__ __nv_bfloat16 g_r2e_h[NRAT * EE];
__device__ __nv_bfloat16 g_r2e_l[NRAT * EE];
__device__ __nv_bfloat16 g_post_h[NN * EE];
__device__ __nv_bfloat16 g_post_l[NN * EE];

__global__ void k_reset() { g_count = 0; }

__global__ void k_build_pairs(const int* __restrict__ lengths) {
    int n = blockIdx.x * blockDim.x + threadIdx.x;
    if (n >= NN) return;
    int len = lengths[n];
    int base = atomicAdd(&g_count, len);
    for (int l = 0; l < len; ++l) g_pairs[base + l] = (n << 6) | l;
}

__global__ void k_pack_emb(const float* __restrict__ u2e, const float* __restrict__ r2e) {
    int i = blockIdx.x * blockDim.x + threadIdx.x;
    if (i < NUSERS * EE) {
        float x = u2e[i];
        __nv_bfloat16 h = __float2bfloat16(x);
        g_u2e_h[i] = h;
        g_u2e_l[i] = __float2bfloat16(x - __bfloat162float(h));
    }
    if (i < NRAT * EE) {
        float x = r2e[i];
        __nv_bfloat16 h = __float2bfloat16(x);
        g_r2e_h[i] = h;
        g_r2e_l[i] = __float2bfloat16(x - __bfloat162float(h));
    }
}

__global__ void k_pack_post() {
    int i = blockIdx.x * blockDim.x + threadIdx.x;
    if (i < NN * EE) {
        float x = g_post[i];
        __nv_bfloat16 h = __float2bfloat16(x);
        g_post_h[i] = h;
        g_post_l[i] = __float2bfloat16(x - __bfloat162float(h));
    }
}

// ---------------- helpers ----------------
__device__ __forceinline__ void ffma2(ull& d, ull a, ull b) {
    asm("fma.rn.f32x2 %0, %1, %2, %0;" : "+l"(d) : "l"(a), "l"(b));
}
__device__ __forceinline__ float hsum2(ull v) {
    float2 p = *(float2*)&v;
    return p.x + p.y;
}
__device__ __forceinline__ void cp16(void* dst, const void* src) {
    unsigned d = (unsigned)__cvta_generic_to_shared(dst);
    asm volatile("cp.async.cg.shared.global [%0], [%1], 16;" :: "r"(d), "l"(src));
}
__device__ __forceinline__ void cp_commit() {
    asm volatile("cp.async.commit_group;");
}
__device__ __forceinline__ void cp_wait0() {
    asm volatile("cp.async.wait_group 0;" ::: "memory");
}
__device__ __forceinline__ u32 packbf(float x0, float x1) {
    u32 r;
    asm("cvt.rn.bf16x2.f32 %0, %1, %2;" : "=r"(r) : "f"(x1), "f"(x0));
    return r;
}

__device__ __forceinline__ void load_wt(const float* __restrict__ Wg, float* __restrict__ Wt,
                                        int K, int tid, int nthr) {
    for (int i = tid; i < K * 64; i += nthr) {
        int k = i >> 6, f = i & 63;
        Wt[(k >> 2) * 256 + ((f >> 2) + (f & 3) * 16) * 4 + (k & 3)] = Wg[i];
    }
}

#define MAP_SLOTS() \
    const int fslot = (((tid >> 5) & 3) << 2) + (tid & 3); \
    const int ibase = ((tid >> 7) << 5) + ((tid >> 2) & 7);

__device__ __forceinline__ void tile_gemm_p(
    const float* __restrict__ Wt, const float* __restrict__ bias,
    const float* __restrict__ inA, int ldA, int K,
    float* __restrict__ out, int ldO, int tid)
{
    MAP_SLOTS();
    ull acc[4][4];
    #pragma unroll
    for (int j = 0; j < 4; ++j)
        #pragma unroll
        for (int ff = 0; ff < 4; ++ff) acc[j][ff] = 0ull;

    const float* wp = Wt + fslot * 4;
    const float* xp = inA + ibase * ldA;
    const int nkb = K >> 2;
    #pragma unroll 4
    for (int kb = 0; kb < nkb; ++kb) {
        ulonglong2 w[4];
        #pragma unroll
        for (int ff = 0; ff < 4; ++ff)
            w[ff] = *(const ulonglong2*)(wp + kb * 256 + ff * 64);
        ulonglong2 x[4];
        #pragma unroll
        for (int j = 0; j < 4; ++j)
            x[j] = *(const ulonglong2*)(xp + j * (8 * ldA) + kb * 4);
        #pragma unroll
        for (int j = 0; j < 4; ++j)
            #pragma unroll
            for (int ff = 0; ff < 4; ++ff) {
                ffma2(acc[j][ff], x[j].x, w[ff].x);
                ffma2(acc[j][ff], x[j].y, w[ff].y);
            }
    }
    float4 b4 = ((const float4*)bias)[fslot];
    #pragma unroll
    for (int j = 0; j < 4; ++j) {
        float4 v;
        v.x = fmaxf(hsum2(acc[j][0]) + b4.x, 0.f);
        v.y = fmaxf(hsum2(acc[j][1]) + b4.y, 0.f);
        v.z = fmaxf(hsum2(acc[j][2]) + b4.z, 0.f);
        v.w = fmaxf(hsum2(acc[j][3]) + b4.w, 0.f);
        *(float4*)(out + (ibase + 8 * j) * ldO + fslot * 4) = v;
    }
}

// ---------------- post kernel (fp32, proven) ----------------
#define LDIN 132

struct SmemPost {
    float Wet[128 * 64];
    float bWe[64];
    float in[64 * LDIN];
    int   cix[64];
};

__global__ void __launch_bounds__(256, 1) k_post(
    const float* __restrict__ content, const float* __restrict__ Weg,
    const float* __restrict__ bWeg, const int* __restrict__ pr_content)
{
    extern __shared__ float smem_raw[];
    SmemPost& s = *(SmemPost*)smem_raw;
    int tid = threadIdx.x;
    load_wt(Weg, s.Wet, 128, tid, 256);
    if (tid < 64) { s.bWe[tid] = bWeg[tid]; s.cix[tid] = pr_content[blockIdx.x * 64 + tid]; }
    __syncthreads();
    for (int v = tid; v < 64 * 32; v += 256) {
        int it = v >> 5, sub = v & 31;
        cp16(s.in + it * LDIN + sub * 4,
             content + (size_t)s.cix[it] * 128 + sub * 4);
    }
    cp_commit(); cp_wait0();
    __syncthreads();
    tile_gemm_p(s.Wet, s.bWe, s.in, LDIN, 128,
                g_post + (size_t)blockIdx.x * 64 * 64, 64, tid);
}

// ==================== WMMA main kernel ====================
// Plane stride 72 bf16 = 144B -> ldmatrix rows hit distinct banks.
#define PLD 72
#define SLD 36   // fp32 scratch stride (144B)

struct SmemW {
    __nv_bfloat16 pAh[128 * PLD], pAl[128 * PLD];
    __nv_bfloat16 pBh[128 * PLD], pBl[128 * PLD];
    __nv_bfloat16 Wt[12][64 * PLD];   // {W1a,W1b,W2,A1a,A1b,A2} x {hi,lo}
    float scratch[128 * SLD];
    float bias[5 * 64];               // b1,b2,bA1,bA2,A3
    int   idx[4 * 128];               // pn,pl,uix,rix
};

// build one 64-K weight stage: rows [k0,k0+64) of Wg -> hi/lo planes (row-major K x 64, ld=PLD)
__device__ __forceinline__ void build_w(const float* __restrict__ Wg, int k0,
                                        __nv_bfloat16* wh, __nv_bfloat16* wl, int tid) {
    for (int i = tid; i < 64 * 64; i += 256) {
        int k = i >> 6, f = i & 63;
        float w = Wg[(k0 + k) * 64 + f];
        __nv_bfloat16 h = __float2bfloat16(w);
        wh[k * PLD + f] = h;
        wl[k * PLD + f] = __float2bfloat16(w - __bfloat162float(h));
    }
}

// one 64-K MMA stage: acc += [Ah|Al] x [Bh|Bl] (3-term split)
__device__ __forceinline__ void mma_stage(
    FragC acc[2][2],
    const __nv_bfloat16* Ah, const __nv_bfloat16* Al,
    const __nv_bfloat16* Bh, const __nv_bfloat16* Bl, int rb, int ch)
{
    #pragma unroll
    for (int kt = 0; kt < 4; ++kt) {
        FragA ah[2], al[2];
        #pragma unroll
        for (int r = 0; r < 2; ++r) {
            wmma::load_matrix_sync(ah[r], Ah + (rb * 32 + r * 16) * PLD + kt * 16, PLD);
            wmma::load_matrix_sync(al[r], Al + (rb * 32 + r * 16) * PLD + kt * 16, PLD);
        }
        #pragma unroll
        for (int c = 0; c < 2; ++c) {
            FragB bh, bl;
            wmma::load_matrix_sync(bh, Bh + kt * 16 * PLD + ch * 32 + c * 16, PLD);
            wmma::load_matrix_sync(bl, Bl + kt * 16 * PLD + ch * 32 + c * 16, PLD);
            #pragma unroll
            for (int r = 0; r < 2; ++r) {
                wmma::mma_sync(acc[r][c], ah[r], bh, acc[r][c]);
                wmma::mma_sync(acc[r][c], al[r], bh, acc[r][c]);
                wmma::mma_sync(acc[r][c], ah[r], bl, acc[r][c]);
            }
        }
    }
}

// store acc -> scratch in two 32-col chunks; relu+bias; repack hi/lo into dh/dl;
// optionally STG fp32 rows to g_o. Ends synced.
__device__ __forceinline__ void store_convert(
    SmemW& s, FragC acc[2][2], const float* __restrict__ bias,
    __nv_bfloat16* dh, __nv_bfloat16* dl, int rb, int ch, int tid,
    bool og, const int* __restrict__ pn, const int* __restrict__ pl)
{
    #pragma unroll
    for (int cc = 0; cc < 2; ++cc) {
        if (ch == cc) {
            #pragma unroll
            for (int r = 0; r < 2; ++r)
                #pragma unroll
                for (int c = 0; c < 2; ++c)
                    wmma::store_matrix_sync(s.scratch + (rb * 32 + r * 16) * SLD + c * 16,
                                            acc[r][c], SLD, wmma::mem_row_major);
        }
        __syncthreads();
        {
            int m = tid >> 1, c0 = (tid & 1) << 4;
            float v[16];
            #pragma unroll
            for (int q = 0; q < 4; ++q) {
                float4 x = *(const float4*)(s.scratch + m * SLD + c0 + q * 4);
                v[q * 4]     = fmaxf(x.x + bias[cc * 32 + c0 + q * 4],     0.f);
                v[q * 4 + 1] = fmaxf(x.y + bias[cc * 32 + c0 + q * 4 + 1], 0.f);
                v[q * 4 + 2] = fmaxf(x.z + bias[cc * 32 + c0 + q * 4 + 2], 0.f);
                v[q * 4 + 3] = fmaxf(x.w + bias[cc * 32 + c0 + q * 4 + 3], 0.f);
            }
            u32 hp[8], lp[8];
            #pragma unroll
            for (int e = 0; e < 8; ++e) {
                float x0 = v[2 * e], x1 = v[2 * e + 1];
                u32 hw = packbf(x0, x1);
                float h0 = __uint_as_float(hw << 16);
                float h1 = __uint_as_float(hw & 0xffff0000u);
                hp[e] = hw;
                lp[e] = packbf(x0 - h0, x1 - h1);
            }
            int col = cc * 32 + c0;
            *(uint4*)(dh + m * PLD + col)     = make_uint4(hp[0], hp[1], hp[2], hp[3]);
            *(uint4*)(dh + m * PLD + col + 8) = make_uint4(hp[4], hp[5], hp[6], hp[7]);
            *(uint4*)(dl + m * PLD + col)     = make_uint4(lp[0], lp[1], lp[2], lp[3]);
            *(uint4*)(dl + m * PLD + col + 8) = make_uint4(lp[4], lp[5], lp[6], lp[7]);
            if (og) {
                float* orow = g_o + ((size_t)pn[m] * LL + pl[m]) * 64 + col;
                #pragma unroll
                for (int q = 0; q < 4; ++q)
                    *(float4*)(orow + q * 4) =
                        make_float4(v[q * 4], v[q * 4 + 1], v[q * 4 + 2], v[q * 4 + 3]);
            }
        }
        __syncthreads();
    }
}

__global__ void __launch_bounds__(256, 1) k_main_w(
    const float* __restrict__ W1g, const float* __restrict__ b1g,
    const float* __restrict__ W2g, const float* __restrict__ b2g,
    const float* __restrict__ A1g, const float* __restrict__ bA1g,
    const float* __restrict__ A2g, const float* __restrict__ bA2g,
    const float* __restrict__ A3g, const float* __restrict__ bA3g,
    const int* __restrict__ pu, const int* __restrict__ pr)
{
    extern __shared__ char smraw[];
    SmemW& s = *(SmemW*)smraw;
    const int tid = threadIdx.x;

    build_w(W1g, 0,  s.Wt[0],  s.Wt[1],  tid);
    build_w(W1g, 64, s.Wt[2],  s.Wt[3],  tid);
    build_w(W2g, 0,  s.Wt[4],  s.Wt[5],  tid);
    build_w(A1g, 0,  s.Wt[6],  s.Wt[7],  tid);
    build_w(A1g, 64, s.Wt[8],  s.Wt[9],  tid);
    build_w(A2g, 0,  s.Wt[10], s.Wt[11], tid);
    if (tid < 64) {
        s.bias[tid] = b1g[tid]; s.bias[64 + tid] = b2g[tid];
        s.bias[128 + tid] = bA1g[tid]; s.bias[192 + tid] = bA2g[tid];
        s.bias[256 + tid] = A3g[tid];
    }
    const float bA3 = bA3g[0];
    int* pn  = s.idx;
    int* pl  = s.idx + 128;
    int* uix = s.idx + 256;
    int* rix = s.idx + 384;
    __syncthreads();

    const int warp = tid >> 5, rb = warp >> 1, ch = warp & 1;
    const int total = g_count;
    const int ntiles = (total + 127) >> 7;
    FragC acc[2][2];

    for (int t = blockIdx.x; t < ntiles; t += gridDim.x) {
        if (tid < 128) {
            int e = (t << 7) + tid;
            int pair = (e < total) ? g_pairs[e] : 0;   // pad -> (0,0), benign dup
            int n = pair >> 6, l = pair & 63;
            pn[tid] = n; pl[tid] = l;
            uix[tid] = pu[n * LL + l];
            rix[tid] = pr[n * LL + l];
        }
        __syncthreads();

        // gather u -> planeA, r -> planeB (hi/lo)
        for (int v = tid; v < 128 * 8; v += 256) {
            int m = v >> 3, c = v & 7;
            cp16(s.pAh + m * PLD + c * 8, g_u2e_h + (size_t)uix[m] * 64 + c * 8);
            cp16(s.pAl + m * PLD + c * 8, g_u2e_l + (size_t)uix[m] * 64 + c * 8);
            cp16(s.pBh + m * PLD + c * 8, g_r2e_h + (size_t)rix[m] * 64 + c * 8);
            cp16(s.pBl + m * PLD + c * 8, g_r2e_l + (size_t)rix[m] * 64 + c * 8);
        }
        cp_commit(); cp_wait0();
        __syncthreads();

        // L1 = x = relu([u;r] W1 + b1)
        #pragma unroll
        for (int r = 0; r < 2; ++r)
            #pragma unroll
            for (int c = 0; c < 2; ++c) wmma::fill_fragment(acc[r][c], 0.f);
        mma_stage(acc, s.pAh, s.pAl, s.Wt[0], s.Wt[1], rb, ch);
        mma_stage(acc, s.pBh, s.pBl, s.Wt[2], s.Wt[3], rb, ch);
        __syncthreads();

        // post gather into planeB (overlaps x-convert + L2)
        for (int v = tid; v < 128 * 8; v += 256) {
            int m = v >> 3, c = v & 7;
            cp16(s.pBh + m * PLD + c * 8, g_post_h + (size_t)pn[m] * 64 + c * 8);
            cp16(s.pBl + m * PLD + c * 8, g_post_l + (size_t)pn[m] * 64 + c * 8);
        }
        cp_commit();

        store_convert(s, acc, s.bias, s.pAh, s.pAl, rb, ch, tid, false, pn, pl); // x -> planeA

        // L2 = o = relu(x W2 + b2)
        #pragma unroll
        for (int r = 0; r < 2; ++r)
            #pragma unroll
            for (int c = 0; c < 2; ++c) wmma::fill_fragment(acc[r][c], 0.f);
        mma_stage(acc, s.pAh, s.pAl, s.Wt[4], s.Wt[5], rb, ch);
        cp_wait0();
        __syncthreads();

        store_convert(s, acc, s.bias + 64, s.pAh, s.pAl, rb, ch, tid, true, pn, pl); // o

        // L3 = a1 = relu([o;post] A1 + bA1)
        #pragma unroll
        for (int r = 0; r < 2; ++r)
            #pragma unroll
            for (int c = 0; c < 2; ++c) wmma::fill_fragment(acc[r][c], 0.f);
        mma_stage(acc, s.pAh, s.pAl, s.Wt[6], s.Wt[7], rb, ch);
        mma_stage(acc, s.pBh, s.pBl, s.Wt[8], s.Wt[9], rb, ch);
        __syncthreads();

        store_convert(s, acc, s.bias + 128, s.pAh, s.pAl, rb, ch, tid, false, pn, pl); // a1

        // L4 = a2 (relu folded into logit pass)
        #pragma unroll
        for (int r = 0; r < 2; ++r)
            #pragma unroll
            for (int c = 0; c < 2; ++c) wmma::fill_fragment(acc[r][c], 0.f);
        mma_stage(acc, s.pAh, s.pAl, s.Wt[10], s.Wt[11], rb, ch);
        __syncthreads();

        // logit = relu(a2 + bA2) . A3 + bA3
        float lg = 0.f;
        #pragma unroll
        for (int cc = 0; cc < 2; ++cc) {
            if (ch == cc) {
                #pragma unroll
                for (int r = 0; r < 2; ++r)
                    #pragma unroll
                    for (int c = 0; c < 2; ++c)
                        wmma::store_matrix_sync(s.scratch + (rb * 32 + r * 16) * SLD + c * 16,
                                                acc[r][c], SLD, wmma::mem_row_major);
            }
            __syncthreads();
            if (tid < 128) {
                #pragma unroll 8
                for (int j = 0; j < 32; ++j) {
                    float v = fmaxf(s.scratch[tid * SLD + j] + s.bias[192 + cc * 32 + j], 0.f);
                    lg = fmaf(v, s.bias[256 + cc * 32 + j], lg);
                }
            }
            __syncthreads();
        }
        if (tid < 128)
            g_logits[pn[tid] * LL + pl[tid]] = lg + bA3;
        __syncthreads();
    }
}

// ---------------- finalize (fp32, proven) ----------------
struct SmemFin {
    float Ow[128 * 64];
    float bOw[64];
    float att[8][64];
    float in[8][128];
    float red[8][4][64];
};

__global__ void __launch_bounds__(512, 1) k_fin(
    const float* __restrict__ Owg, const float* __restrict__ bOwg,
    const int* __restrict__ lengths, float* __restrict__ out)
{
    extern __shared__ float smem_raw[];
    SmemFin& s = *(SmemFin*)smem_raw;
    int tid = threadIdx.x;
    for (int i = tid; i < 128 * 64; i += 512) s.Ow[i] = Owg[i];
    if (tid < 64) s.bOw[tid] = bOwg[tid];
    __syncthreads();

    const int g = tid >> 6;
    const int gt = tid & 63;

    for (int base = blockIdx.x * 8; base < NN; base += gridDim.x * 8) {
        int n = base + g;
        int len = lengths[n];

        if (gt < 32) {
            int lane = gt;
            float l0 = (lane < len)      ? g_logits[n * LL + lane]      : -INFINITY;
            float l1 = (lane + 32 < len) ? g_logits[n * LL + lane + 32] : -INFINITY;
            float m = fmaxf(l0, l1);
            #pragma unroll
            for (int off = 16; off >= 1; off >>= 1)
                m = fmaxf(m, __shfl_xor_sync(0xffffffffu, m, off));
            float e0 = (lane < len)      ? expf(l0 - m) : 0.f;
            float e1 = (lane + 32 < len) ? expf(l1 - m) : 0.f;
            float sum = e0 + e1;
            #pragma unroll
            for (int off = 16; off >= 1; off >>= 1)
                sum += __shfl_xor_sync(0xffffffffu, sum, off);
            float inv = 1.f / sum;
            s.att[g][lane] = e0 * inv; s.att[g][lane + 32] = e1 * inv;
        } else {
            int f0 = gt - 32;
            s.in[g][64 + f0]      = g_post[n * 64 + f0];
            s.in[g][64 + f0 + 32] = g_post[n * 64 + f0 + 32];
        }
        __syncthreads();

        {
            const float* orow = g_o + (size_t)n * LL * 64 + gt;
            float h0 = 0.f, h1 = 0.f, h2 = 0.f, h3 = 0.f;
            int l = 0;
            for (; l + 3 < len; l += 4) {
                h0 = fmaf(s.att[g][l],     orow[(size_t)(l)     * 64], h0);
                h1 = fmaf(s.att[g][l + 1], orow[(size_t)(l + 1) * 64], h1);
                h2 = fmaf(s.att[g][l + 2], orow[(size_t)(l + 2) * 64], h2);
                h3 = fmaf(s.att[g][l + 3], orow[(size_t)(l + 3) * 64], h3);
            }
            for (; l < len; ++l)
                h0 = fmaf(s.att[g][l], orow[(size_t)l * 64], h0);
            s.in[g][gt] = (h0 + h1) + (h2 + h3);
        }
        __syncthreads();

        {
            int fslot = gt & 15, kslot = gt >> 4;
            float4 acc2 = make_float4(0.f, 0.f, 0.f, 0.f);
            const float* Wp = s.Ow + fslot * 4;
            #pragma unroll 8
            for (int k = kslot * 32; k < kslot * 32 + 32; ++k) {
                float xv = s.in[g][k];
                float4 w = *(const float4*)(Wp + k * 64);
                acc2.x = fmaf(xv, w.x, acc2.x); acc2.y = fmaf(xv, w.y, acc2.y);
                acc2.z = fmaf(xv, w.z, acc2.z); acc2.w = fmaf(xv, w.w, acc2.w);
            }
            *(float4*)(&s.red[g][kslot][fslot * 4]) = acc2;
        }
        __syncthreads();

        {
            float v = s.bOw[gt] + s.red[g][0][gt] + s.red[g][1][gt]
                                + s.red[g][2][gt] + s.red[g][3][gt];
            out[n * 64 + gt] = fmaxf(v, 0.f);
        }
        __syncthreads();
    }
}

// ---------------- launch ----------------
extern "C" void kernel_launch(void* const* d_in, const int* in_sizes, int n_in,
                              void* d_out, int out_size)
{
    const float* u2e     = (const float*)d_in[0];
    const float* r2e     = (const float*)d_in[1];
    const float* content = (const float*)d_in[2];
    const float* We_w = (const float*)d_in[3];  const float* We_b = (const float*)d_in[4];
    const float* W1_w = (const float*)d_in[5];  const float* W1_b = (const float*)d_in[6];
    const float* W2_w = (const float*)d_in[7];  const float* W2_b = (const float*)d_in[8];
    const float* A1_w = (const float*)d_in[9];  const float* A1_b = (const float*)d_in[10];
    const float* A2_w = (const float*)d_in[11]; const float* A2_b = (const float*)d_in[12];
    const float* A3_w = (const float*)d_in[13]; const float* A3_b = (const float*)d_in[14];
    const float* Ow_w = (const float*)d_in[15]; const float* Ow_b = (const float*)d_in[16];
    const int* pu      = (const int*)d_in[18];
    const int* pr      = (const int*)d_in[19];
    const int* lengths = (const int*)d_in[20];
    const int* prc     = (const int*)d_in[21];
    float* out = (float*)d_out;

    static int nsm = 0;
    if (nsm == 0) {
        cudaDeviceGetAttribute(&nsm, cudaDevAttrMultiProcessorCount, 0);
        cudaFuncSetAttribute(k_main_w, cudaFuncAttributeMaxDynamicSharedMemorySize, (int)sizeof(SmemW));
        cudaFuncSetAttribute(k_post, cudaFuncAttributeMaxDynamicSharedMemorySize, (int)sizeof(SmemPost));
        cudaFuncSetAttribute(k_fin,  cudaFuncAttributeMaxDynamicSharedMemorySize, (int)sizeof(SmemFin));
    }

    k_reset<<<1, 1>>>();
    k_build_pairs<<<NN / 256, 256>>>(lengths);
    k_pack_emb<<<(NUSERS * EE + 511) / 512, 512>>>(u2e, r2e);
    k_post<<<NN / 64, 256, sizeof(SmemPost)>>>(content, We_w, We_b, prc);
    k_pack_post<<<(NN * EE + 511) / 512, 512>>>();
    k_main_w<<<nsm, 256, sizeof(SmemW)>>>(W1_w, W1_b, W2_w, W2_b,
                                          A1_w, A1_b, A2_w, A2_b, A3_w, A3_b, pu, pr);
    k_fin<<<nsm, 512, sizeof(SmemFin)>>>(Ow_w, Ow_b, lengths, out);
}

// round 11
// speedup vs baseline: 1.9734x; 1.0034x over previous
#include <cuda_runtime.h>
#include <cuda_bf16.h>
#include <mma.h>
#include <cstdint>
#include <math.h>

#define NN 16384
#define LL 50
#define EE 64
#define CEDIM 128
#define NUSERS 100000
#define NRAT 6

typedef unsigned long long ull;
typedef unsigned int u32;

using namespace nvcuda;
typedef wmma::fragment<wmma::matrix_a, 16, 16, 16, __nv_bfloat16, wmma::row_major> FragA;
typedef wmma::fragment<wmma::matrix_b, 16, 16, 16, __nv_bfloat16, wmma::row_major> FragB;
typedef wmma::fragment<wmma::accumulator, 16, 16, 16, float> FragC;

// ---------------- device scratch ----------------
__device__ float g_post[NN * EE];                    // 4 MB
__device__ float g_o[(size_t)NN * LL * EE];          // 210 MB
__device__ float g_logits[NN * LL];                  // 3.3 MB
__device__ int   g_pairs[NN * LL];                   // 3.3 MB
__device__ int   g_count;
// packed hi/lo bf16 tables
__device__ __nv_bfloat16 g_u2e_h[NUSERS * EE];
__device__ __nv_bfloat16 g_u2e_l[NUSERS * EE];
__device__ __nv_bfloat16 g_r2e_h[NRAT * EE];
__device__ __nv_bfloat16 g_r2e_l[NRAT * EE];
__device__ __nv_bfloat16 g_post_h[NN * EE];
__device__ __nv_bfloat16 g_post_l[NN * EE];

__global__ void k_reset() { g_count = 0; }

__global__ void k_build_pairs(const int* __restrict__ lengths) {
    int n = blockIdx.x * blockDim.x + threadIdx.x;
    if (n >= NN) return;
    int len = lengths[n];
    int base = atomicAdd(&g_count, len);
    for (int l = 0; l < len; ++l) g_pairs[base + l] = (n << 6) | l;
}

__global__ void k_pack_emb(const float* __restrict__ u2e, const float* __restrict__ r2e) {
    int i = blockIdx.x * blockDim.x + threadIdx.x;
    if (i < NUSERS * EE) {
        float x = u2e[i];
        __nv_bfloat16 h = __float2bfloat16(x);
        g_u2e_h[i] = h;
        g_u2e_l[i] = __float2bfloat16(x - __bfloat162float(h));
    }
    if (i < NRAT * EE) {
        float x = r2e[i];
        __nv_bfloat16 h = __float2bfloat16(x);
        g_r2e_h[i] = h;
        g_r2e_l[i] = __float2bfloat16(x - __bfloat162float(h));
    }
}

__global__ void k_pack_post() {
    int i = blockIdx.x * blockDim.x + threadIdx.x;
    if (i < NN * EE) {
        float x = g_post[i];
        __nv_bfloat16 h = __float2bfloat16(x);
        g_post_h[i] = h;
        g_post_l[i] = __float2bfloat16(x - __bfloat162float(h));
    }
}

// ---------------- helpers ----------------
__device__ __forceinline__ void ffma2(ull& d, ull a, ull b) {
    asm("fma.rn.f32x2 %0, %1, %2, %0;" : "+l"(d) : "l"(a), "l"(b));
}
__device__ __forceinline__ float hsum2(ull v) {
    float2 p = *(float2*)&v;
    return p.x + p.y;
}
__device__ __forceinline__ void cp16(void* dst, const void* src) {
    unsigned d = (unsigned)__cvta_generic_to_shared(dst);
    asm volatile("cp.async.cg.shared.global [%0], [%1], 16;" :: "r"(d), "l"(src));
}
__device__ __forceinline__ void cp_commit() {
    asm volatile("cp.async.commit_group;");
}
__device__ __forceinline__ void cp_wait0() {
    asm volatile("cp.async.wait_group 0;" ::: "memory");
}
__device__ __forceinline__ u32 packbf(float x0, float x1) {
    u32 r;
    asm("cvt.rn.bf16x2.f32 %0, %1, %2;" : "=r"(r) : "f"(x1), "f"(x0));
    return r;
}

__device__ __forceinline__ void load_wt(const float* __restrict__ Wg, float* __restrict__ Wt,
                                        int K, int tid, int nthr) {
    for (int i = tid; i < K * 64; i += nthr) {
        int k = i >> 6, f = i & 63;
        Wt[(k >> 2) * 256 + ((f >> 2) + (f & 3) * 16) * 4 + (k & 3)] = Wg[i];
    }
}

#define MAP_SLOTS() \
    const int fslot = (((tid >> 5) & 3) << 2) + (tid & 3); \
    const int ibase = ((tid >> 7) << 5) + ((tid >> 2) & 7);

__device__ __forceinline__ void tile_gemm_p(
    const float* __restrict__ Wt, const float* __restrict__ bias,
    const float* __restrict__ inA, int ldA, int K,
    float* __restrict__ out, int ldO, int tid)
{
    MAP_SLOTS();
    ull acc[4][4];
    #pragma unroll
    for (int j = 0; j < 4; ++j)
        #pragma unroll
        for (int ff = 0; ff < 4; ++ff) acc[j][ff] = 0ull;

    const float* wp = Wt + fslot * 4;
    const float* xp = inA + ibase * ldA;
    const int nkb = K >> 2;
    #pragma unroll 4
    for (int kb = 0; kb < nkb; ++kb) {
        ulonglong2 w[4];
        #pragma unroll
        for (int ff = 0; ff < 4; ++ff)
            w[ff] = *(const ulonglong2*)(wp + kb * 256 + ff * 64);
        ulonglong2 x[4];
        #pragma unroll
        for (int j = 0; j < 4; ++j)
            x[j] = *(const ulonglong2*)(xp + j * (8 * ldA) + kb * 4);
        #pragma unroll
        for (int j = 0; j < 4; ++j)
            #pragma unroll
            for (int ff = 0; ff < 4; ++ff) {
                ffma2(acc[j][ff], x[j].x, w[ff].x);
                ffma2(acc[j][ff], x[j].y, w[ff].y);
            }
    }
    float4 b4 = ((const float4*)bias)[fslot];
    #pragma unroll
    for (int j = 0; j < 4; ++j) {
        float4 v;
        v.x = fmaxf(hsum2(acc[j][0]) + b4.x, 0.f);
        v.y = fmaxf(hsum2(acc[j][1]) + b4.y, 0.f);
        v.z = fmaxf(hsum2(acc[j][2]) + b4.z, 0.f);
        v.w = fmaxf(hsum2(acc[j][3]) + b4.w, 0.f);
        *(float4*)(out + (ibase + 8 * j) * ldO + fslot * 4) = v;
    }
}

// ---------------- post kernel (fp32, proven) ----------------
#define LDIN 132

struct SmemPost {
    float Wet[128 * 64];
    float bWe[64];
    float in[64 * LDIN];
    int   cix[64];
};

__global__ void __launch_bounds__(256, 1) k_post(
    const float* __restrict__ content, const float* __restrict__ Weg,
    const float* __restrict__ bWeg, const int* __restrict__ pr_content)
{
    extern __shared__ float smem_raw[];
    SmemPost& s = *(SmemPost*)smem_raw;
    int tid = threadIdx.x;
    load_wt(Weg, s.Wet, 128, tid, 256);
    if (tid < 64) { s.bWe[tid] = bWeg[tid]; s.cix[tid] = pr_content[blockIdx.x * 64 + tid]; }
    __syncthreads();
    for (int v = tid; v < 64 * 32; v += 256) {
        int it = v >> 5, sub = v & 31;
        cp16(s.in + it * LDIN + sub * 4,
             content + (size_t)s.cix[it] * 128 + sub * 4);
    }
    cp_commit(); cp_wait0();
    __syncthreads();
    tile_gemm_p(s.Wet, s.bWe, s.in, LDIN, 128,
                g_post + (size_t)blockIdx.x * 64 * 64, 64, tid);
}

// ==================== WMMA main kernel ====================
// Plane stride 72 bf16 = 144B -> ldmatrix rows hit distinct banks.
#define PLD 72
#define SLD 36   // fp32 scratch stride (144B)

struct SmemW {
    __nv_bfloat16 pAh[128 * PLD], pAl[128 * PLD];
    __nv_bfloat16 pBh[128 * PLD], pBl[128 * PLD];
    __nv_bfloat16 Wt[12][64 * PLD];   // {W1a,W1b,W2,A1a,A1b,A2} x {hi,lo}
    float scratch[128 * SLD];
    float bias[5 * 64];               // b1,b2,bA1,bA2,A3
    int   idx[4 * 128];               // pn,pl,uix,rix
};

// build one 64-K weight stage: rows [k0,k0+64) of Wg -> hi/lo planes (row-major K x 64, ld=PLD)
__device__ __forceinline__ void build_w(const float* __restrict__ Wg, int k0,
                                        __nv_bfloat16* wh, __nv_bfloat16* wl, int tid) {
    for (int i = tid; i < 64 * 64; i += 256) {
        int k = i >> 6, f = i & 63;
        float w = Wg[(k0 + k) * 64 + f];
        __nv_bfloat16 h = __float2bfloat16(w);
        wh[k * PLD + f] = h;
        wl[k * PLD + f] = __float2bfloat16(w - __bfloat162float(h));
    }
}

// one 64-K MMA stage: acc += [Ah|Al] x [Bh|Bl] (3-term split)
__device__ __forceinline__ void mma_stage(
    FragC acc[2][2],
    const __nv_bfloat16* Ah, const __nv_bfloat16* Al,
    const __nv_bfloat16* Bh, const __nv_bfloat16* Bl, int rb, int ch)
{
    #pragma unroll
    for (int kt = 0; kt < 4; ++kt) {
        FragA ah[2], al[2];
        #pragma unroll
        for (int r = 0; r < 2; ++r) {
            wmma::load_matrix_sync(ah[r], Ah + (rb * 32 + r * 16) * PLD + kt * 16, PLD);
            wmma::load_matrix_sync(al[r], Al + (rb * 32 + r * 16) * PLD + kt * 16, PLD);
        }
        #pragma unroll
        for (int c = 0; c < 2; ++c) {
            FragB bh, bl;
            wmma::load_matrix_sync(bh, Bh + kt * 16 * PLD + ch * 32 + c * 16, PLD);
            wmma::load_matrix_sync(bl, Bl + kt * 16 * PLD + ch * 32 + c * 16, PLD);
            #pragma unroll
            for (int r = 0; r < 2; ++r) {
                wmma::mma_sync(acc[r][c], ah[r], bh, acc[r][c]);
                wmma::mma_sync(acc[r][c], al[r], bh, acc[r][c]);
                wmma::mma_sync(acc[r][c], ah[r], bl, acc[r][c]);
            }
        }
    }
}

// store acc -> scratch in two 32-col chunks; relu+bias; repack hi/lo into dh/dl;
// optionally STG fp32 rows to g_o. Ends synced.
__device__ __forceinline__ void store_convert(
    SmemW& s, FragC acc[2][2], const float* __restrict__ bias,
    __nv_bfloat16* dh, __nv_bfloat16* dl, int rb, int ch, int tid,
    bool og, const int* __restrict__ pn, const int* __restrict__ pl)
{
    #pragma unroll
    for (int cc = 0; cc < 2; ++cc) {
        if (ch == cc) {
            #pragma unroll
            for (int r = 0; r < 2; ++r)
                #pragma unroll
                for (int c = 0; c < 2; ++c)
                    wmma::store_matrix_sync(s.scratch + (rb * 32 + r * 16) * SLD + c * 16,
                                            acc[r][c], SLD, wmma::mem_row_major);
        }
        __syncthreads();
        {
            int m = tid >> 1, c0 = (tid & 1) << 4;
            float v[16];
            #pragma unroll
            for (int q = 0; q < 4; ++q) {
                float4 x = *(const float4*)(s.scratch + m * SLD + c0 + q * 4);
                v[q * 4]     = fmaxf(x.x + bias[cc * 32 + c0 + q * 4],     0.f);
                v[q * 4 + 1] = fmaxf(x.y + bias[cc * 32 + c0 + q * 4 + 1], 0.f);
                v[q * 4 + 2] = fmaxf(x.z + bias[cc * 32 + c0 + q * 4 + 2], 0.f);
                v[q * 4 + 3] = fmaxf(x.w + bias[cc * 32 + c0 + q * 4 + 3], 0.f);
            }
            u32 hp[8], lp[8];
            #pragma unroll
            for (int e = 0; e < 8; ++e) {
                float x0 = v[2 * e], x1 = v[2 * e + 1];
                u32 hw = packbf(x0, x1);
                float h0 = __uint_as_float(hw << 16);
                float h1 = __uint_as_float(hw & 0xffff0000u);
                hp[e] = hw;
                lp[e] = packbf(x0 - h0, x1 - h1);
            }
            int col = cc * 32 + c0;
            *(uint4*)(dh + m * PLD + col)     = make_uint4(hp[0], hp[1], hp[2], hp[3]);
            *(uint4*)(dh + m * PLD + col + 8) = make_uint4(hp[4], hp[5], hp[6], hp[7]);
            *(uint4*)(dl + m * PLD + col)     = make_uint4(lp[0], lp[1], lp[2], lp[3]);
            *(uint4*)(dl + m * PLD + col + 8) = make_uint4(lp[4], lp[5], lp[6], lp[7]);
            if (og) {
                float* orow = g_o + ((size_t)pn[m] * LL + pl[m]) * 64 + col;
                #pragma unroll
                for (int q = 0; q < 4; ++q)
                    *(float4*)(orow + q * 4) =
                        make_float4(v[q * 4], v[q * 4 + 1], v[q * 4 + 2], v[q * 4 + 3]);
            }
        }
        __syncthreads();
    }
}

__global__ void __launch_bounds__(256, 1) k_main_w(
    const float* __restrict__ W1g, const float* __restrict__ b1g,
    const float* __restrict__ W2g, const float* __restrict__ b2g,
    const float* __restrict__ A1g, const float* __restrict__ bA1g,
    const float* __restrict__ A2g, const float* __restrict__ bA2g,
    const float* __restrict__ A3g, const float* __restrict__ bA3g,
    const int* __restrict__ pu, const int* __restrict__ pr)
{
    extern __shared__ char smraw[];
    SmemW& s = *(SmemW*)smraw;
    const int tid = threadIdx.x;

    build_w(W1g, 0,  s.Wt[0],  s.Wt[1],  tid);
    build_w(W1g, 64, s.Wt[2],  s.Wt[3],  tid);
    build_w(W2g, 0,  s.Wt[4],  s.Wt[5],  tid);
    build_w(A1g, 0,  s.Wt[6],  s.Wt[7],  tid);
    build_w(A1g, 64, s.Wt[8],  s.Wt[9],  tid);
    build_w(A2g, 0,  s.Wt[10], s.Wt[11], tid);
    if (tid < 64) {
        s.bias[tid] = b1g[tid]; s.bias[64 + tid] = b2g[tid];
        s.bias[128 + tid] = bA1g[tid]; s.bias[192 + tid] = bA2g[tid];
        s.bias[256 + tid] = A3g[tid];
    }
    const float bA3 = bA3g[0];
    int* pn  = s.idx;
    int* pl  = s.idx + 128;
    int* uix = s.idx + 256;
    int* rix = s.idx + 384;
    __syncthreads();

    const int warp = tid >> 5, rb = warp >> 1, ch = warp & 1;
    const int total = g_count;
    const int ntiles = (total + 127) >> 7;
    FragC acc[2][2];

    for (int t = blockIdx.x; t < ntiles; t += gridDim.x) {
        if (tid < 128) {
            int e = (t << 7) + tid;
            int pair = (e < total) ? g_pairs[e] : 0;   // pad -> (0,0), benign dup
            int n = pair >> 6, l = pair & 63;
            pn[tid] = n; pl[tid] = l;
            uix[tid] = pu[n * LL + l];
            rix[tid] = pr[n * LL + l];
        }
        __syncthreads();

        // gather u -> planeA, r -> planeB (hi/lo)
        for (int v = tid; v < 128 * 8; v += 256) {
            int m = v >> 3, c = v & 7;
            cp16(s.pAh + m * PLD + c * 8, g_u2e_h + (size_t)uix[m] * 64 + c * 8);
            cp16(s.pAl + m * PLD + c * 8, g_u2e_l + (size_t)uix[m] * 64 + c * 8);
            cp16(s.pBh + m * PLD + c * 8, g_r2e_h + (size_t)rix[m] * 64 + c * 8);
            cp16(s.pBl + m * PLD + c * 8, g_r2e_l + (size_t)rix[m] * 64 + c * 8);
        }
        cp_commit(); cp_wait0();
        __syncthreads();

        // L1 = x = relu([u;r] W1 + b1)
        #pragma unroll
        for (int r = 0; r < 2; ++r)
            #pragma unroll
            for (int c = 0; c < 2; ++c) wmma::fill_fragment(acc[r][c], 0.f);
        mma_stage(acc, s.pAh, s.pAl, s.Wt[0], s.Wt[1], rb, ch);
        mma_stage(acc, s.pBh, s.pBl, s.Wt[2], s.Wt[3], rb, ch);
        __syncthreads();

        // post gather into planeB (overlaps x-convert + L2)
        for (int v = tid; v < 128 * 8; v += 256) {
            int m = v >> 3, c = v & 7;
            cp16(s.pBh + m * PLD + c * 8, g_post_h + (size_t)pn[m] * 64 + c * 8);
            cp16(s.pBl + m * PLD + c * 8, g_post_l + (size_t)pn[m] * 64 + c * 8);
        }
        cp_commit();

        store_convert(s, acc, s.bias, s.pAh, s.pAl, rb, ch, tid, false, pn, pl); // x -> planeA

        // L2 = o = relu(x W2 + b2)
        #pragma unroll
        for (int r = 0; r < 2; ++r)
            #pragma unroll
            for (int c = 0; c < 2; ++c) wmma::fill_fragment(acc[r][c], 0.f);
        mma_stage(acc, s.pAh, s.pAl, s.Wt[4], s.Wt[5], rb, ch);
        cp_wait0();
        __syncthreads();

        store_convert(s, acc, s.bias + 64, s.pAh, s.pAl, rb, ch, tid, true, pn, pl); // o

        // L3 = a1 = relu([o;post] A1 + bA1)
        #pragma unroll
        for (int r = 0; r < 2; ++r)
            #pragma unroll
            for (int c = 0; c < 2; ++c) wmma::fill_fragment(acc[r][c], 0.f);
        mma_stage(acc, s.pAh, s.pAl, s.Wt[6], s.Wt[7], rb, ch);
        mma_stage(acc, s.pBh, s.pBl, s.Wt[8], s.Wt[9], rb, ch);
        __syncthreads();

        store_convert(s, acc, s.bias + 128, s.pAh, s.pAl, rb, ch, tid, false, pn, pl); // a1

        // L4 = a2 (relu folded into logit pass)
        #pragma unroll
        for (int r = 0; r < 2; ++r)
            #pragma unroll
            for (int c = 0; c < 2; ++c) wmma::fill_fragment(acc[r][c], 0.f);
        mma_stage(acc, s.pAh, s.pAl, s.Wt[10], s.Wt[11], rb, ch);
        __syncthreads();

        // logit = relu(a2 + bA2) . A3 + bA3
        float lg = 0.f;
        #pragma unroll
        for (int cc = 0; cc < 2; ++cc) {
            if (ch == cc) {
                #pragma unroll
                for (int r = 0; r < 2; ++r)
                    #pragma unroll
                    for (int c = 0; c < 2; ++c)
                        wmma::store_matrix_sync(s.scratch + (rb * 32 + r * 16) * SLD + c * 16,
                                                acc[r][c], SLD, wmma::mem_row_major);
            }
            __syncthreads();
            if (tid < 128) {
                #pragma unroll 8
                for (int j = 0; j < 32; ++j) {
                    float v = fmaxf(s.scratch[tid * SLD + j] + s.bias[192 + cc * 32 + j], 0.f);
                    lg = fmaf(v, s.bias[256 + cc * 32 + j], lg);
                }
            }
            __syncthreads();
        }
        if (tid < 128)
            g_logits[pn[tid] * LL + pl[tid]] = lg + bA3;
        __syncthreads();
    }
}

// ---------------- finalize (fp32, proven) ----------------
struct SmemFin {
    float Ow[128 * 64];
    float bOw[64];
    float att[8][64];
    float in[8][128];
    float red[8][4][64];
};

__global__ void __launch_bounds__(512, 1) k_fin(
    const float* __restrict__ Owg, const float* __restrict__ bOwg,
    const int* __restrict__ lengths, float* __restrict__ out)
{
    extern __shared__ float smem_raw[];
    SmemFin& s = *(SmemFin*)smem_raw;
    int tid = threadIdx.x;
    for (int i = tid; i < 128 * 64; i += 512) s.Ow[i] = Owg[i];
    if (tid < 64) s.bOw[tid] = bOwg[tid];
    __syncthreads();

    const int g = tid >> 6;
    const int gt = tid & 63;

    for (int base = blockIdx.x * 8; base < NN; base += gridDim.x * 8) {
        int n = base + g;
        int len = lengths[n];

        if (gt < 32) {
            int lane = gt;
            float l0 = (lane < len)      ? g_logits[n * LL + lane]      : -INFINITY;
            float l1 = (lane + 32 < len) ? g_logits[n * LL + lane + 32] : -INFINITY;
            float m = fmaxf(l0, l1);
            #pragma unroll
            for (int off = 16; off >= 1; off >>= 1)
                m = fmaxf(m, __shfl_xor_sync(0xffffffffu, m, off));
            float e0 = (lane < len)      ? expf(l0 - m) : 0.f;
            float e1 = (lane + 32 < len) ? expf(l1 - m) : 0.f;
            float sum = e0 + e1;
            #pragma unroll
            for (int off = 16; off >= 1; off >>= 1)
                sum += __shfl_xor_sync(0xffffffffu, sum, off);
            float inv = 1.f / sum;
            s.att[g][lane] = e0 * inv; s.att[g][lane + 32] = e1 * inv;
        } else {
            int f0 = gt - 32;
            s.in[g][64 + f0]      = g_post[n * 64 + f0];
            s.in[g][64 + f0 + 32] = g_post[n * 64 + f0 + 32];
        }
        __syncthreads();

        {
            const float* orow = g_o + (size_t)n * LL * 64 + gt;
            float h0 = 0.f, h1 = 0.f, h2 = 0.f, h3 = 0.f;
            int l = 0;
            for (; l + 3 < len; l += 4) {
                h0 = fmaf(s.att[g][l],     orow[(size_t)(l)     * 64], h0);
                h1 = fmaf(s.att[g][l + 1], orow[(size_t)(l + 1) * 64], h1);
                h2 = fmaf(s.att[g][l + 2], orow[(size_t)(l + 2) * 64], h2);
                h3 = fmaf(s.att[g][l + 3], orow[(size_t)(l + 3) * 64], h3);
            }
            for (; l < len; ++l)
                h0 = fmaf(s.att[g][l], orow[(size_t)l * 64], h0);
            s.in[g][gt] = (h0 + h1) + (h2 + h3);
        }
        __syncthreads();

        {
            int fslot = gt & 15, kslot = gt >> 4;
            float4 acc2 = make_float4(0.f, 0.f, 0.f, 0.f);
            const float* Wp = s.Ow + fslot * 4;
            #pragma unroll 8
            for (int k = kslot * 32; k < kslot * 32 + 32; ++k) {
                float xv = s.in[g][k];
                float4 w = *(const float4*)(Wp + k * 64);
                acc2.x = fmaf(xv, w.x, acc2.x); acc2.y = fmaf(xv, w.y, acc2.y);
                acc2.z = fmaf(xv, w.z, acc2.z); acc2.w = fmaf(xv, w.w, acc2.w);
            }
            *(float4*)(&s.red[g][kslot][fslot * 4]) = acc2;
        }
        __syncthreads();

        {
            float v = s.bOw[gt] + s.red[g][0][gt] + s.red[g][1][gt]
                                + s.red[g][2][gt] + s.red[g][3][gt];
            out[n * 64 + gt] = fmaxf(v, 0.f);
        }
        __syncthreads();
    }
}

// ---------------- launch ----------------
extern "C" void kernel_launch(void* const* d_in, const int* in_sizes, int n_in,
                              void* d_out, int out_size)
{
    const float* u2e     = (const float*)d_in[0];
    const float* r2e     = (const float*)d_in[1];
    const float* content = (const float*)d_in[2];
    const float* We_w = (const float*)d_in[3];  const float* We_b = (const float*)d_in[4];
    const float* W1_w = (const float*)d_in[5];  const float* W1_b = (const float*)d_in[6];
    const float* W2_w = (const float*)d_in[7];  const float* W2_b = (const float*)d_in[8];
    const float* A1_w = (const float*)d_in[9];  const float* A1_b = (const float*)d_in[10];
    const float* A2_w = (const float*)d_in[11]; const float* A2_b = (const float*)d_in[12];
    const float* A3_w = (const float*)d_in[13]; const float* A3_b = (const float*)d_in[14];
    const float* Ow_w = (const float*)d_in[15]; const float* Ow_b = (const float*)d_in[16];
    const int* pu      = (const int*)d_in[18];
    const int* pr      = (const int*)d_in[19];
    const int* lengths = (const int*)d_in[20];
    const int* prc     = (const int*)d_in[21];
    float* out = (float*)d_out;

    static int nsm = 0;
    if (nsm == 0) {
        cudaDeviceGetAttribute(&nsm, cudaDevAttrMultiProcessorCount, 0);
        cudaFuncSetAttribute(k_main_w, cudaFuncAttributeMaxDynamicSharedMemorySize, (int)sizeof(SmemW));
        cudaFuncSetAttribute(k_post, cudaFuncAttributeMaxDynamicSharedMemorySize, (int)sizeof(SmemPost));
        cudaFuncSetAttribute(k_fin,  cudaFuncAttributeMaxDynamicSharedMemorySize, (int)sizeof(SmemFin));
    }

    k_reset<<<1, 1>>>();
    k_build_pairs<<<NN / 256, 256>>>(lengths);
    k_pack_emb<<<(NUSERS * EE + 511) / 512, 512>>>(u2e, r2e);
    k_post<<<NN / 64, 256, sizeof(SmemPost)>>>(content, We_w, We_b, prc);
    k_pack_post<<<(NN * EE + 511) / 512, 512>>>();
    k_main_w<<<nsm, 256, sizeof(SmemW)>>>(W1_w, W1_b, W2_w, W2_b,
                                          A1_w, A1_b, A2_w, A2_b, A3_w, A3_b, pu, pr);
    k_fin<<<nsm, 512, sizeof(SmemFin)>>>(Ow_w, Ow_b, lengths, out);
}